// round 2
// baseline (speedup 1.0000x reference)
#include <cuda_runtime.h>
#include <math.h>

// ---------------------------------------------------------------------------
// Problem constants
// ---------------------------------------------------------------------------
#define BB 2
#define TT 2048
#define DD 1024
#define HH 16
#define HDIM 64
#define ROWS (BB * TT)          // 4096
#define D3 (3 * DD)             // 3072
#define D4 (4 * DD)             // 4096

// ---------------------------------------------------------------------------
// Scratch (static device globals; allocation inside kernel_launch is illegal)
// ---------------------------------------------------------------------------
__device__ float g_xn [ROWS * DD];   // LN output (reused for ln1 and ln2)
__device__ float g_qkv[ROWS * D3];   // qkv projection
__device__ float g_y  [ROWS * DD];   // attention output
__device__ float g_x2 [ROWS * DD];   // residual after attention
__device__ float g_fc [ROWS * D4];   // gelu(h @ w_fc)

// ---------------------------------------------------------------------------
// LayerNorm: one block per row (1024 elements), 256 threads * float4
// ---------------------------------------------------------------------------
__global__ void ln_kernel(const float* __restrict__ x,
                          const float* __restrict__ g,
                          const float* __restrict__ b,
                          float* __restrict__ out) {
    __shared__ float s_sum[8];
    __shared__ float s_sq[8];
    const int row = blockIdx.x;
    const int tid = threadIdx.x;
    const float4* xr = (const float4*)(x + (size_t)row * DD);
    float4 v = xr[tid];
    float s  = v.x + v.y + v.z + v.w;
    float ss = v.x * v.x + v.y * v.y + v.z * v.z + v.w * v.w;
    #pragma unroll
    for (int off = 16; off > 0; off >>= 1) {
        s  += __shfl_xor_sync(0xffffffffu, s,  off);
        ss += __shfl_xor_sync(0xffffffffu, ss, off);
    }
    if ((tid & 31) == 0) { s_sum[tid >> 5] = s; s_sq[tid >> 5] = ss; }
    __syncthreads();
    float ts = 0.f, tss = 0.f;
    #pragma unroll
    for (int i = 0; i < 8; i++) { ts += s_sum[i]; tss += s_sq[i]; }
    const float mean = ts * (1.0f / DD);
    const float var  = tss * (1.0f / DD) - mean * mean;
    const float rstd = rsqrtf(var + 1e-5f);
    float4 gv = ((const float4*)g)[tid];
    float4 bv = ((const float4*)b)[tid];
    float4 o;
    o.x = (v.x - mean) * rstd * gv.x + bv.x;
    o.y = (v.y - mean) * rstd * gv.y + bv.y;
    o.z = (v.z - mean) * rstd * gv.z + bv.z;
    o.w = (v.w - mean) * rstd * gv.w + bv.w;
    ((float4*)(out + (size_t)row * DD))[tid] = o;
}

// ---------------------------------------------------------------------------
// SGEMM: C[M,N] = A[M,K] @ B[K,N]  (+ residual / gelu epilogue)
// 128x128 tile, K-chunk 8, 256 threads, 8x8 per-thread microtile.
// All dims here are multiples of 128 / 8 -> no bounds checks.
// EPI: 0 = store, 1 = store A@B + R, 2 = store gelu(A@B)
// ---------------------------------------------------------------------------
__device__ __forceinline__ float gelu_exact(float x) {
    return 0.5f * x * (1.0f + erff(x * 0.70710678118654752f));
}

template<int EPI>
__global__ __launch_bounds__(256, 2)
void sgemm_kernel(const float* __restrict__ A, const float* __restrict__ B,
                  const float* __restrict__ R, float* __restrict__ C,
                  int M, int N, int K) {
    __shared__ float As[8][128];
    __shared__ float Bs[8][128];

    const int tid  = threadIdx.x;
    const int row0 = blockIdx.y * 128;
    const int col0 = blockIdx.x * 128;
    const int tx = tid & 15;          // 16 col groups
    const int ty = tid >> 4;          // 16 row groups

    const int arow = tid >> 1;        // 0..127
    const int ac4  = (tid & 1) * 4;   // 0 or 4
    const int brow = tid >> 5;        // 0..7
    const int bc4  = (tid & 31) * 4;  // 0..124

    const float* Aptr = A + (size_t)(row0 + arow) * K + ac4;
    const float* Bptr = B + (size_t)brow * N + col0 + bc4;

    float acc[8][8];
    #pragma unroll
    for (int i = 0; i < 8; i++)
        #pragma unroll
        for (int j = 0; j < 8; j++) acc[i][j] = 0.f;

    for (int k0 = 0; k0 < K; k0 += 8) {
        float4 av = *(const float4*)(Aptr + k0);
        float4 bv = *(const float4*)(Bptr + (size_t)k0 * N);
        __syncthreads();
        As[ac4 + 0][arow] = av.x;
        As[ac4 + 1][arow] = av.y;
        As[ac4 + 2][arow] = av.z;
        As[ac4 + 3][arow] = av.w;
        *(float4*)&Bs[brow][bc4] = bv;
        __syncthreads();
        #pragma unroll
        for (int k = 0; k < 8; k++) {
            float a[8], b[8];
            *(float4*)&a[0] = *(const float4*)&As[k][ty * 8];
            *(float4*)&a[4] = *(const float4*)&As[k][ty * 8 + 4];
            *(float4*)&b[0] = *(const float4*)&Bs[k][tx * 8];
            *(float4*)&b[4] = *(const float4*)&Bs[k][tx * 8 + 4];
            #pragma unroll
            for (int i = 0; i < 8; i++)
                #pragma unroll
                for (int j = 0; j < 8; j++)
                    acc[i][j] += a[i] * b[j];
        }
    }

    #pragma unroll
    for (int i = 0; i < 8; i++) {
        const size_t r = (size_t)(row0 + ty * 8 + i);
        #pragma unroll
        for (int j4 = 0; j4 < 2; j4++) {
            const int col = col0 + tx * 8 + j4 * 4;
            float4 v;
            v.x = acc[i][j4 * 4 + 0];
            v.y = acc[i][j4 * 4 + 1];
            v.z = acc[i][j4 * 4 + 2];
            v.w = acc[i][j4 * 4 + 3];
            if (EPI == 1) {
                float4 rv = *(const float4*)(R + r * N + col);
                v.x += rv.x; v.y += rv.y; v.z += rv.z; v.w += rv.w;
            } else if (EPI == 2) {
                v.x = gelu_exact(v.x); v.y = gelu_exact(v.y);
                v.z = gelu_exact(v.z); v.w = gelu_exact(v.w);
            }
            *(float4*)(C + r * N + col) = v;
        }
    }
}

// ---------------------------------------------------------------------------
// Causal flash attention (fp32).
// Grid: (T/64 q-tiles, B*H). 256 threads = (tx 16, ty 16).
// Each thread: 4x4 of S, 4(q-rows) x 4(d-cols) of O accumulator.
// Dynamic smem: Qs[64][64] | Ks/Ps[64][68] | Vs[64][64]  (50176 B)
// ---------------------------------------------------------------------------
#define ATTN_SMEM_BYTES ((64*64 + 64*68 + 64*64) * 4)

__global__ __launch_bounds__(256, 1)
void attn_kernel(const float* __restrict__ qkv, float* __restrict__ y) {
    extern __shared__ float smem[];
    float* Qs = smem;               // stride 64
    float* Ks = smem + 64 * 64;     // stride 68 (doubles as P buffer)
    float* Vs = Ks + 64 * 68;       // stride 64

    const int qt = blockIdx.x;                 // q tile index (0..31)
    const int bh = blockIdx.y;                 // b*H + h
    const int bb = bh >> 4;
    const int hh = bh & 15;

    const float* qbase = qkv + (size_t)bb * TT * D3 + hh * HDIM;
    const float* kbase = qbase + DD;
    const float* vbase = qbase + 2 * DD;

    const int tid = threadIdx.x;
    const int tx = tid & 15;
    const int ty = tid >> 4;

    // Load Q tile (scaled by 1/sqrt(HD) = 0.125)
    for (int i = tid; i < 64 * 16; i += 256) {
        const int r = i >> 4, c4 = (i & 15) * 4;
        float4 v = *(const float4*)(qbase + (size_t)(qt * 64 + r) * D3 + c4);
        v.x *= 0.125f; v.y *= 0.125f; v.z *= 0.125f; v.w *= 0.125f;
        *(float4*)&Qs[r * 64 + c4] = v;
    }

    float o[4][4];
    float m[4], l[4];
    #pragma unroll
    for (int a = 0; a < 4; a++) {
        m[a] = -INFINITY; l[a] = 0.f;
        #pragma unroll
        for (int c = 0; c < 4; c++) o[a][c] = 0.f;
    }

    const int nkt = qt + 1;   // causal: only tiles <= qt
    for (int kt = 0; kt < nkt; kt++) {
        __syncthreads();   // previous-iteration readers done (also covers Q load)
        for (int i = tid; i < 64 * 16; i += 256) {
            const int r = i >> 4, c4 = (i & 15) * 4;
            *(float4*)&Ks[r * 68 + c4] =
                *(const float4*)(kbase + (size_t)(kt * 64 + r) * D3 + c4);
            *(float4*)&Vs[r * 64 + c4] =
                *(const float4*)(vbase + (size_t)(kt * 64 + r) * D3 + c4);
        }
        __syncthreads();

        // S = Q K^T (already scaled)
        float s[4][4];
        #pragma unroll
        for (int a = 0; a < 4; a++)
            #pragma unroll
            for (int b = 0; b < 4; b++) s[a][b] = 0.f;

        #pragma unroll 4
        for (int d4 = 0; d4 < 16; d4++) {
            float4 qa[4], kb[4];
            #pragma unroll
            for (int a = 0; a < 4; a++)
                qa[a] = *(const float4*)&Qs[(ty * 4 + a) * 64 + d4 * 4];
            #pragma unroll
            for (int b = 0; b < 4; b++)
                kb[b] = *(const float4*)&Ks[(tx * 4 + b) * 68 + d4 * 4];
            #pragma unroll
            for (int a = 0; a < 4; a++)
                #pragma unroll
                for (int b = 0; b < 4; b++)
                    s[a][b] += qa[a].x * kb[b].x + qa[a].y * kb[b].y
                             + qa[a].z * kb[b].z + qa[a].w * kb[b].w;
        }

        // causal mask on the diagonal tile
        if (kt == qt) {
            #pragma unroll
            for (int a = 0; a < 4; a++)
                #pragma unroll
                for (int b = 0; b < 4; b++)
                    if (tx * 4 + b > ty * 4 + a) s[a][b] = -1e30f;
        }

        // online softmax
        float alpha[4], ls[4];
        #pragma unroll
        for (int a = 0; a < 4; a++) {
            float mt = fmaxf(fmaxf(s[a][0], s[a][1]), fmaxf(s[a][2], s[a][3]));
            #pragma unroll
            for (int off = 1; off < 16; off <<= 1)
                mt = fmaxf(mt, __shfl_xor_sync(0xffffffffu, mt, off));
            const float mnew = fmaxf(m[a], mt);
            alpha[a] = __expf(m[a] - mnew);
            m[a] = mnew;
            float sum = 0.f;
            #pragma unroll
            for (int b = 0; b < 4; b++) {
                const float p = __expf(s[a][b] - mnew);
                s[a][b] = p;
                sum += p;
            }
            #pragma unroll
            for (int off = 1; off < 16; off <<= 1)
                sum += __shfl_xor_sync(0xffffffffu, sum, off);
            ls[a] = sum;
        }

        __syncthreads();   // everyone done reading Ks before P overwrite
        #pragma unroll
        for (int a = 0; a < 4; a++) {
            l[a] = l[a] * alpha[a] + ls[a];
            #pragma unroll
            for (int c = 0; c < 4; c++) o[a][c] *= alpha[a];
            #pragma unroll
            for (int b = 0; b < 4; b++)
                Ks[(ty * 4 + a) * 68 + tx * 4 + b] = s[a][b];   // P tile
        }
        __syncthreads();

        // O += P @ V   (thread covers d-cols tx*4..+3)
        #pragma unroll 4
        for (int j = 0; j < 64; j++) {
            const float4 v = *(const float4*)&Vs[j * 64 + tx * 4];
            #pragma unroll
            for (int a = 0; a < 4; a++) {
                const float p = Ks[(ty * 4 + a) * 68 + j];
                o[a][0] += p * v.x;
                o[a][1] += p * v.y;
                o[a][2] += p * v.z;
                o[a][3] += p * v.w;
            }
        }
    }

    // normalize + store: y[b, qt*64 + row, h*64 + col]
    #pragma unroll
    for (int a = 0; a < 4; a++) {
        const float inv = 1.0f / l[a];
        float4 v;
        v.x = o[a][0] * inv; v.y = o[a][1] * inv;
        v.z = o[a][2] * inv; v.w = o[a][3] * inv;
        const size_t t = (size_t)bb * TT + qt * 64 + ty * 4 + a;
        *(float4*)(y + t * DD + hh * HDIM + tx * 4) = v;
    }
}

// ---------------------------------------------------------------------------
// Launch
// ---------------------------------------------------------------------------
extern "C" void kernel_launch(void* const* d_in, const int* in_sizes, int n_in,
                              void* d_out, int out_size) {
    const float* x      = (const float*)d_in[0];
    const float* w_attn = (const float*)d_in[1];
    const float* w_proj = (const float*)d_in[2];
    const float* w_fc   = (const float*)d_in[3];
    const float* w_out  = (const float*)d_in[4];
    const float* ln1_g  = (const float*)d_in[5];
    const float* ln1_b  = (const float*)d_in[6];
    const float* ln2_g  = (const float*)d_in[7];
    const float* ln2_b  = (const float*)d_in[8];
    float* out = (float*)d_out;

    float *p_xn, *p_qkv, *p_y, *p_x2, *p_fc;
    cudaGetSymbolAddress((void**)&p_xn,  g_xn);
    cudaGetSymbolAddress((void**)&p_qkv, g_qkv);
    cudaGetSymbolAddress((void**)&p_y,   g_y);
    cudaGetSymbolAddress((void**)&p_x2,  g_x2);
    cudaGetSymbolAddress((void**)&p_fc,  g_fc);

    cudaFuncSetAttribute(attn_kernel,
                         cudaFuncAttributeMaxDynamicSharedMemorySize,
                         ATTN_SMEM_BYTES);

    // 1) xn = LN1(x)
    ln_kernel<<<ROWS, 256>>>(x, ln1_g, ln1_b, p_xn);

    // 2) qkv = xn @ w_attn           [4096,1024]x[1024,3072]
    sgemm_kernel<0><<<dim3(D3 / 128, ROWS / 128), 256>>>(
        p_xn, w_attn, nullptr, p_qkv, ROWS, D3, DD);

    // 3) y = causal MHA(qkv)
    attn_kernel<<<dim3(TT / 64, BB * HH), 256, ATTN_SMEM_BYTES>>>(p_qkv, p_y);

    // 4) x2 = x + y @ w_proj         [4096,1024]x[1024,1024]
    sgemm_kernel<1><<<dim3(DD / 128, ROWS / 128), 256>>>(
        p_y, w_proj, x, p_x2, ROWS, DD, DD);

    // 5) xn = LN2(x2)
    ln_kernel<<<ROWS, 256>>>(p_x2, ln2_g, ln2_b, p_xn);

    // 6) fc = gelu(xn @ w_fc)        [4096,1024]x[1024,4096]
    sgemm_kernel<2><<<dim3(D4 / 128, ROWS / 128), 256>>>(
        p_xn, w_fc, nullptr, p_fc, ROWS, D4, DD);

    // 7) out = x2 + fc @ w_out       [4096,4096]x[4096,1024]
    sgemm_kernel<1><<<dim3(DD / 128, ROWS / 128), 256>>>(
        p_fc, w_out, p_x2, out, ROWS, DD, D4);
}

// round 4
// speedup vs baseline: 1.7864x; 1.7864x over previous
#include <cuda_runtime.h>
#include <cuda_bf16.h>
#include <math.h>
#include <stdint.h>

// ---------------------------------------------------------------------------
// Problem constants
// ---------------------------------------------------------------------------
#define BB 2
#define TT 2048
#define DD 1024
#define HH 16
#define HDIM 64
#define ROWS (BB * TT)          // 4096
#define D3 (3 * DD)             // 3072
#define D4 (4 * DD)             // 4096

// ---------------------------------------------------------------------------
// Scratch
// ---------------------------------------------------------------------------
__device__ float g_qkv[ROWS * D3];
__device__ float g_x2 [ROWS * DD];

__device__ __nv_bfloat16 g_xn_hi[ROWS * DD], g_xn_lo[ROWS * DD];
__device__ __nv_bfloat16 g_y_hi [ROWS * DD], g_y_lo [ROWS * DD];
__device__ __nv_bfloat16 g_fc_hi[ROWS * D4], g_fc_lo[ROWS * D4];

__device__ __nv_bfloat16 g_wattn_hi[D3 * DD], g_wattn_lo[D3 * DD];
__device__ __nv_bfloat16 g_wproj_hi[DD * DD], g_wproj_lo[DD * DD];
__device__ __nv_bfloat16 g_wfc_hi [D4 * DD], g_wfc_lo [D4 * DD];
__device__ __nv_bfloat16 g_wout_hi[DD * D4], g_wout_lo[DD * D4];

// ---------------------------------------------------------------------------
// Helpers
// ---------------------------------------------------------------------------
__device__ __forceinline__ uint32_t smem_u32(const void* p) {
    uint32_t a;
    asm("{ .reg .u64 t; cvta.to.shared.u64 t, %1; cvt.u32.u64 %0, t; }"
        : "=r"(a) : "l"(p));
    return a;
}

__device__ __forceinline__ void cp16(uint32_t dst, const void* src) {
    asm volatile("cp.async.cg.shared.global [%0], [%1], 16;"
                 :: "r"(dst), "l"(src));
}
__device__ __forceinline__ void cp_commit() {
    asm volatile("cp.async.commit_group;");
}
__device__ __forceinline__ void cp_wait3() {
    asm volatile("cp.async.wait_group 3;");
}

#define LDSM4(d0, d1, d2, d3, addr)                                          \
    asm volatile("ldmatrix.sync.aligned.m8n8.x4.shared.b16 {%0,%1,%2,%3}, [%4];" \
                 : "=r"(d0), "=r"(d1), "=r"(d2), "=r"(d3) : "r"(addr))

#define MMA_BF16(c, a, b)                                                    \
    asm volatile("mma.sync.aligned.m16n8k16.row.col.f32.bf16.bf16.f32 "      \
                 "{%0,%1,%2,%3}, {%4,%5,%6,%7}, {%8,%9}, {%0,%1,%2,%3};"     \
                 : "+f"((c)[0]), "+f"((c)[1]), "+f"((c)[2]), "+f"((c)[3])    \
                 : "r"((a)[0]), "r"((a)[1]), "r"((a)[2]), "r"((a)[3]),       \
                   "r"((b)[0]), "r"((b)[1]))

__device__ __forceinline__ void split_bf16(float v, __nv_bfloat16& h, __nv_bfloat16& l) {
    h = __float2bfloat16(v);
    l = __float2bfloat16(v - __bfloat162float(h));
}

__device__ __forceinline__ void store4bf16(__nv_bfloat16* p,
                                           __nv_bfloat16 a, __nv_bfloat16 b,
                                           __nv_bfloat16 c, __nv_bfloat16 d) {
    __nv_bfloat162 v0; v0.x = a; v0.y = b;
    __nv_bfloat162 v1; v1.x = c; v1.y = d;
    uint2 u;
    u.x = *reinterpret_cast<uint32_t*>(&v0);
    u.y = *reinterpret_cast<uint32_t*>(&v1);
    *reinterpret_cast<uint2*>(p) = u;
}

__device__ __forceinline__ float gelu_exact(float x) {
    return 0.5f * x * (1.0f + erff(x * 0.70710678118654752f));
}

// ---------------------------------------------------------------------------
// Weight transpose + split:  W[K,N] fp32 -> T_hi/T_lo[N,K] bf16
// ---------------------------------------------------------------------------
__global__ void wtrans_kernel(const float* __restrict__ W,
                              __nv_bfloat16* __restrict__ Thi,
                              __nv_bfloat16* __restrict__ Tlo,
                              int K, int N) {
    __shared__ float s[32][33];
    const int n0 = blockIdx.x * 32;
    const int k0 = blockIdx.y * 32;
    const int tx = threadIdx.x, ty = threadIdx.y;
    #pragma unroll
    for (int i = 0; i < 4; i++)
        s[ty + 8 * i][tx] = W[(size_t)(k0 + ty + 8 * i) * N + n0 + tx];
    __syncthreads();
    #pragma unroll
    for (int i = 0; i < 4; i++) {
        const float v = s[tx][ty + 8 * i];
        __nv_bfloat16 h, l;
        split_bf16(v, h, l);
        const size_t o = (size_t)(n0 + ty + 8 * i) * K + k0 + tx;
        Thi[o] = h;
        Tlo[o] = l;
    }
}

// ---------------------------------------------------------------------------
// LayerNorm -> bf16 hi/lo
// ---------------------------------------------------------------------------
__global__ void ln_kernel(const float* __restrict__ x,
                          const float* __restrict__ g,
                          const float* __restrict__ b,
                          __nv_bfloat16* __restrict__ ohi,
                          __nv_bfloat16* __restrict__ olo) {
    __shared__ float s_sum[8];
    __shared__ float s_sq[8];
    const int row = blockIdx.x;
    const int tid = threadIdx.x;
    const float4* xr = (const float4*)(x + (size_t)row * DD);
    float4 v = xr[tid];
    float s  = v.x + v.y + v.z + v.w;
    float ss = v.x * v.x + v.y * v.y + v.z * v.z + v.w * v.w;
    #pragma unroll
    for (int off = 16; off > 0; off >>= 1) {
        s  += __shfl_xor_sync(0xffffffffu, s,  off);
        ss += __shfl_xor_sync(0xffffffffu, ss, off);
    }
    if ((tid & 31) == 0) { s_sum[tid >> 5] = s; s_sq[tid >> 5] = ss; }
    __syncthreads();
    float ts = 0.f, tss = 0.f;
    #pragma unroll
    for (int i = 0; i < 8; i++) { ts += s_sum[i]; tss += s_sq[i]; }
    const float mean = ts * (1.0f / DD);
    const float var  = tss * (1.0f / DD) - mean * mean;
    const float rstd = rsqrtf(var + 1e-5f);
    float4 gv = ((const float4*)g)[tid];
    float4 bv = ((const float4*)b)[tid];
    float o0 = (v.x - mean) * rstd * gv.x + bv.x;
    float o1 = (v.y - mean) * rstd * gv.y + bv.y;
    float o2 = (v.z - mean) * rstd * gv.z + bv.z;
    float o3 = (v.w - mean) * rstd * gv.w + bv.w;
    __nv_bfloat16 h0, l0, h1, l1, h2, l2, h3, l3;
    split_bf16(o0, h0, l0); split_bf16(o1, h1, l1);
    split_bf16(o2, h2, l2); split_bf16(o3, h3, l3);
    const size_t o = (size_t)row * DD + tid * 4;
    store4bf16(ohi + o, h0, h1, h2, h3);
    store4bf16(olo + o, l0, l1, l2, l3);
}

// ---------------------------------------------------------------------------
// bf16-split GEMM via mma.sync: C[M,N] = A[M,K] @ B^T, B stored [N,K].
// CTA 128x128, 8 warps (4m x 2n), warp tile 32x64, K-chunk 32,
// 4-stage cp.async pipeline, padded smem rows (40 bf16 = 80 B).
// EPI: 0 = fp32 ; 1 = fp32 + residual ; 2 = gelu -> bf16 hi/lo
// ---------------------------------------------------------------------------
#define CHUNK 32
#define ROWB 80                      // padded row bytes (40 bf16)
#define ARRB (128 * ROWB)            // 10240 per tensor per stage
#define STAGEB (4 * ARRB)            // 40960
#define NSTAGE 4
#define MM_SMEM (NSTAGE * STAGEB)    // 163840

template<int EPI>
__global__ void __launch_bounds__(256, 1)
mm_kernel(const __nv_bfloat16* __restrict__ Ahi, const __nv_bfloat16* __restrict__ Alo,
          const __nv_bfloat16* __restrict__ Bhi, const __nv_bfloat16* __restrict__ Blo,
          const float* __restrict__ R, float* __restrict__ C,
          __nv_bfloat16* __restrict__ Chi, __nv_bfloat16* __restrict__ Clo,
          int M, int N, int K) {
    extern __shared__ char smem[];
    const uint32_t sbase = smem_u32(smem);

    const int tid  = threadIdx.x;
    const int lane = tid & 31;
    const int wid  = tid >> 5;
    const int wm   = wid & 3;        // 4 warps along M (32 rows each)
    const int wn   = wid >> 2;       // 2 warps along N (64 cols each)
    const int row0 = blockIdx.y * 128;
    const int col0 = blockIdx.x * 128;

    const int i0r = tid >> 2, i0c = tid & 3;
    const int i1r = (tid + 256) >> 2, i1c = tid & 3;

    const int nch = K >> 5;

    float acc[2][8][4];
    #pragma unroll
    for (int mi = 0; mi < 2; mi++)
        #pragma unroll
        for (int ni = 0; ni < 8; ni++)
            #pragma unroll
            for (int j = 0; j < 4; j++) acc[mi][ni][j] = 0.f;

    const uint32_t a_off = (uint32_t)((wm * 32 + (lane & 15)) * ROWB + ((lane >> 4) << 4));
    const uint32_t b_off = (uint32_t)((wn * 64 + ((lane >> 4) << 3) + (lane & 7)) * ROWB
                                      + (((lane >> 3) & 1) << 4));

#define ISSUE(ch)                                                             \
    do {                                                                      \
        const int k0_ = (ch) * CHUNK;                                         \
        const uint32_t sb_ = sbase + ((ch) % NSTAGE) * STAGEB;                \
        cp16(sb_ + 0*ARRB + i0r*ROWB + i0c*16, Ahi + (size_t)(row0+i0r)*K + k0_ + i0c*8); \
        cp16(sb_ + 0*ARRB + i1r*ROWB + i1c*16, Ahi + (size_t)(row0+i1r)*K + k0_ + i1c*8); \
        cp16(sb_ + 1*ARRB + i0r*ROWB + i0c*16, Alo + (size_t)(row0+i0r)*K + k0_ + i0c*8); \
        cp16(sb_ + 1*ARRB + i1r*ROWB + i1c*16, Alo + (size_t)(row0+i1r)*K + k0_ + i1c*8); \
        cp16(sb_ + 2*ARRB + i0r*ROWB + i0c*16, Bhi + (size_t)(col0+i0r)*K + k0_ + i0c*8); \
        cp16(sb_ + 2*ARRB + i1r*ROWB + i1c*16, Bhi + (size_t)(col0+i1r)*K + k0_ + i1c*8); \
        cp16(sb_ + 3*ARRB + i0r*ROWB + i0c*16, Blo + (size_t)(col0+i0r)*K + k0_ + i0c*8); \
        cp16(sb_ + 3*ARRB + i1r*ROWB + i1c*16, Blo + (size_t)(col0+i1r)*K + k0_ + i1c*8); \
    } while (0)

    ISSUE(0); cp_commit();
    ISSUE(1); cp_commit();
    ISSUE(2); cp_commit();

    for (int c = 0; c < nch; c++) {
        if (c + 3 < nch) ISSUE(c + 3);
        cp_commit();
        cp_wait3();
        __syncthreads();

        const uint32_t sb = sbase + (c % NSTAGE) * STAGEB;
        #pragma unroll
        for (int ks = 0; ks < 2; ks++) {
            uint32_t ah[2][4], al[2][4], bh[8][2], bl[8][2];
            #pragma unroll
            for (int mi = 0; mi < 2; mi++) {
                const uint32_t aa = sb + a_off + mi * (16 * ROWB) + ks * 32;
                LDSM4(ah[mi][0], ah[mi][1], ah[mi][2], ah[mi][3], aa);
                LDSM4(al[mi][0], al[mi][1], al[mi][2], al[mi][3], aa + ARRB);
            }
            #pragma unroll
            for (int nb = 0; nb < 4; nb++) {
                const uint32_t ba = sb + 2 * ARRB + b_off + nb * (16 * ROWB) + ks * 32;
                LDSM4(bh[2*nb][0], bh[2*nb][1], bh[2*nb+1][0], bh[2*nb+1][1], ba);
                LDSM4(bl[2*nb][0], bl[2*nb][1], bl[2*nb+1][0], bl[2*nb+1][1], ba + ARRB);
            }
            #pragma unroll
            for (int mi = 0; mi < 2; mi++)
                #pragma unroll
                for (int ni = 0; ni < 8; ni++) {
                    MMA_BF16(acc[mi][ni], ah[mi], bh[ni]);
                    MMA_BF16(acc[mi][ni], ah[mi], bl[ni]);
                    MMA_BF16(acc[mi][ni], al[mi], bh[ni]);
                }
        }
        __syncthreads();
    }

#undef ISSUE

    const int r_b = row0 + wm * 32 + (lane >> 2);
    const int c_b = col0 + wn * 64 + (lane & 3) * 2;
    #pragma unroll
    for (int mi = 0; mi < 2; mi++) {
        #pragma unroll
        for (int half = 0; half < 2; half++) {
            const size_t r = (size_t)(r_b + mi * 16 + half * 8);
            #pragma unroll
            for (int ni = 0; ni < 8; ni++) {
                const int col = c_b + ni * 8;
                float v0 = acc[mi][ni][half * 2 + 0];
                float v1 = acc[mi][ni][half * 2 + 1];
                if (EPI == 0 || EPI == 1) {
                    if (EPI == 1) {
                        const float2 rv = *(const float2*)(R + r * N + col);
                        v0 += rv.x; v1 += rv.y;
                    }
                    float2 o; o.x = v0; o.y = v1;
                    *(float2*)(C + r * N + col) = o;
                } else {
                    v0 = gelu_exact(v0); v1 = gelu_exact(v1);
                    __nv_bfloat16 h0, l0, h1, l1;
                    split_bf16(v0, h0, l0);
                    split_bf16(v1, h1, l1);
                    __nv_bfloat162 hh; hh.x = h0; hh.y = h1;
                    __nv_bfloat162 ll; ll.x = l0; ll.y = l1;
                    *(__nv_bfloat162*)(Chi + r * N + col) = hh;
                    *(__nv_bfloat162*)(Clo + r * N + col) = ll;
                }
            }
        }
    }
}

// ---------------------------------------------------------------------------
// Causal flash attention (fp32 SIMT), outputs bf16 hi/lo.
// ---------------------------------------------------------------------------
#define ATTN_SMEM_BYTES ((64*64 + 64*68 + 64*64) * 4)

__global__ __launch_bounds__(256, 1)
void attn_kernel(const float* __restrict__ qkv,
                 __nv_bfloat16* __restrict__ yhi,
                 __nv_bfloat16* __restrict__ ylo) {
    extern __shared__ float fsm[];
    float* Qs = fsm;
    float* Ks = fsm + 64 * 64;
    float* Vs = Ks + 64 * 68;

    const int qt = blockIdx.x;
    const int bh = blockIdx.y;
    const int bb = bh >> 4;
    const int hh = bh & 15;

    const float* qbase = qkv + (size_t)bb * TT * D3 + hh * HDIM;
    const float* kbase = qbase + DD;
    const float* vbase = qbase + 2 * DD;

    const int tid = threadIdx.x;
    const int tx = tid & 15;
    const int ty = tid >> 4;

    for (int i = tid; i < 64 * 16; i += 256) {
        const int r = i >> 4, c4 = (i & 15) * 4;
        float4 v = *(const float4*)(qbase + (size_t)(qt * 64 + r) * D3 + c4);
        v.x *= 0.125f; v.y *= 0.125f; v.z *= 0.125f; v.w *= 0.125f;
        *(float4*)&Qs[r * 64 + c4] = v;
    }

    float o[4][4];
    float m[4], l[4];
    #pragma unroll
    for (int a = 0; a < 4; a++) {
        m[a] = -INFINITY; l[a] = 0.f;
        #pragma unroll
        for (int c = 0; c < 4; c++) o[a][c] = 0.f;
    }

    const int nkt = qt + 1;
    for (int kt = 0; kt < nkt; kt++) {
        __syncthreads();
        for (int i = tid; i < 64 * 16; i += 256) {
            const int r = i >> 4, c4 = (i & 15) * 4;
            *(float4*)&Ks[r * 68 + c4] =
                *(const float4*)(kbase + (size_t)(kt * 64 + r) * D3 + c4);
            *(float4*)&Vs[r * 64 + c4] =
                *(const float4*)(vbase + (size_t)(kt * 64 + r) * D3 + c4);
        }
        __syncthreads();

        float s[4][4];
        #pragma unroll
        for (int a = 0; a < 4; a++)
            #pragma unroll
            for (int b = 0; b < 4; b++) s[a][b] = 0.f;

        #pragma unroll 4
        for (int d4 = 0; d4 < 16; d4++) {
            float4 qa[4], kb[4];
            #pragma unroll
            for (int a = 0; a < 4; a++)
                qa[a] = *(const float4*)&Qs[(ty * 4 + a) * 64 + d4 * 4];
            #pragma unroll
            for (int b = 0; b < 4; b++)
                kb[b] = *(const float4*)&Ks[(tx * 4 + b) * 68 + d4 * 4];
            #pragma unroll
            for (int a = 0; a < 4; a++)
                #pragma unroll
                for (int b = 0; b < 4; b++)
                    s[a][b] += qa[a].x * kb[b].x + qa[a].y * kb[b].y
                             + qa[a].z * kb[b].z + qa[a].w * kb[b].w;
        }

        if (kt == qt) {
            #pragma unroll
            for (int a = 0; a < 4; a++)
                #pragma unroll
                for (int b = 0; b < 4; b++)
                    if (tx * 4 + b > ty * 4 + a) s[a][b] = -1e30f;
        }

        float alpha[4], ls[4];
        #pragma unroll
        for (int a = 0; a < 4; a++) {
            float mt = fmaxf(fmaxf(s[a][0], s[a][1]), fmaxf(s[a][2], s[a][3]));
            #pragma unroll
            for (int off = 1; off < 16; off <<= 1)
                mt = fmaxf(mt, __shfl_xor_sync(0xffffffffu, mt, off));
            const float mnew = fmaxf(m[a], mt);
            alpha[a] = __expf(m[a] - mnew);
            m[a] = mnew;
            float sum = 0.f;
            #pragma unroll
            for (int b = 0; b < 4; b++) {
                const float p = __expf(s[a][b] - mnew);
                s[a][b] = p;
                sum += p;
            }
            #pragma unroll
            for (int off = 1; off < 16; off <<= 1)
                sum += __shfl_xor_sync(0xffffffffu, sum, off);
            ls[a] = sum;
        }

        __syncthreads();
        #pragma unroll
        for (int a = 0; a < 4; a++) {
            l[a] = l[a] * alpha[a] + ls[a];
            #pragma unroll
            for (int c = 0; c < 4; c++) o[a][c] *= alpha[a];
            #pragma unroll
            for (int b = 0; b < 4; b++)
                Ks[(ty * 4 + a) * 68 + tx * 4 + b] = s[a][b];
        }
        __syncthreads();

        #pragma unroll 4
        for (int j = 0; j < 64; j++) {
            const float4 v = *(const float4*)&Vs[j * 64 + tx * 4];
            #pragma unroll
            for (int a = 0; a < 4; a++) {
                const float p = Ks[(ty * 4 + a) * 68 + j];
                o[a][0] += p * v.x;
                o[a][1] += p * v.y;
                o[a][2] += p * v.z;
                o[a][3] += p * v.w;
            }
        }
    }

    #pragma unroll
    for (int a = 0; a < 4; a++) {
        const float inv = 1.0f / l[a];
        const float v0 = o[a][0] * inv, v1 = o[a][1] * inv;
        const float v2 = o[a][2] * inv, v3 = o[a][3] * inv;
        __nv_bfloat16 h0, l0b, h1, l1b, h2, l2b, h3, l3b;
        split_bf16(v0, h0, l0b); split_bf16(v1, h1, l1b);
        split_bf16(v2, h2, l2b); split_bf16(v3, h3, l3b);
        const size_t t = (size_t)bb * TT + qt * 64 + ty * 4 + a;
        const size_t off = t * DD + hh * HDIM + tx * 4;
        store4bf16(yhi + off, h0, h1, h2, h3);
        store4bf16(ylo + off, l0b, l1b, l2b, l3b);
    }
}

// ---------------------------------------------------------------------------
// Launch
// ---------------------------------------------------------------------------
extern "C" void kernel_launch(void* const* d_in, const int* in_sizes, int n_in,
                              void* d_out, int out_size) {
    const float* x      = (const float*)d_in[0];
    const float* w_attn = (const float*)d_in[1];
    const float* w_proj = (const float*)d_in[2];
    const float* w_fc   = (const float*)d_in[3];
    const float* w_out  = (const float*)d_in[4];
    const float* ln1_g  = (const float*)d_in[5];
    const float* ln1_b  = (const float*)d_in[6];
    const float* ln2_g  = (const float*)d_in[7];
    const float* ln2_b  = (const float*)d_in[8];
    float* out = (float*)d_out;

    float *p_qkv, *p_x2;
    __nv_bfloat16 *p_xn_hi, *p_xn_lo, *p_y_hi, *p_y_lo, *p_fc_hi, *p_fc_lo;
    __nv_bfloat16 *p_wa_hi, *p_wa_lo, *p_wp_hi, *p_wp_lo;
    __nv_bfloat16 *p_wf_hi, *p_wf_lo, *p_wo_hi, *p_wo_lo;
    cudaGetSymbolAddress((void**)&p_qkv,   g_qkv);
    cudaGetSymbolAddress((void**)&p_x2,    g_x2);
    cudaGetSymbolAddress((void**)&p_xn_hi, g_xn_hi);
    cudaGetSymbolAddress((void**)&p_xn_lo, g_xn_lo);
    cudaGetSymbolAddress((void**)&p_y_hi,  g_y_hi);
    cudaGetSymbolAddress((void**)&p_y_lo,  g_y_lo);
    cudaGetSymbolAddress((void**)&p_fc_hi, g_fc_hi);
    cudaGetSymbolAddress((void**)&p_fc_lo, g_fc_lo);
    cudaGetSymbolAddress((void**)&p_wa_hi, g_wattn_hi);
    cudaGetSymbolAddress((void**)&p_wa_lo, g_wattn_lo);
    cudaGetSymbolAddress((void**)&p_wp_hi, g_wproj_hi);
    cudaGetSymbolAddress((void**)&p_wp_lo, g_wproj_lo);
    cudaGetSymbolAddress((void**)&p_wf_hi, g_wfc_hi);
    cudaGetSymbolAddress((void**)&p_wf_lo, g_wfc_lo);
    cudaGetSymbolAddress((void**)&p_wo_hi, g_wout_hi);
    cudaGetSymbolAddress((void**)&p_wo_lo, g_wout_lo);

    cudaFuncSetAttribute(attn_kernel,
                         cudaFuncAttributeMaxDynamicSharedMemorySize, ATTN_SMEM_BYTES);
    cudaFuncSetAttribute(mm_kernel<0>,
                         cudaFuncAttributeMaxDynamicSharedMemorySize, MM_SMEM);
    cudaFuncSetAttribute(mm_kernel<1>,
                         cudaFuncAttributeMaxDynamicSharedMemorySize, MM_SMEM);
    cudaFuncSetAttribute(mm_kernel<2>,
                         cudaFuncAttributeMaxDynamicSharedMemorySize, MM_SMEM);

    const dim3 tb(32, 8);

    wtrans_kernel<<<dim3(D3 / 32, DD / 32), tb>>>(w_attn, p_wa_hi, p_wa_lo, DD, D3);
    wtrans_kernel<<<dim3(DD / 32, DD / 32), tb>>>(w_proj, p_wp_hi, p_wp_lo, DD, DD);
    wtrans_kernel<<<dim3(D4 / 32, DD / 32), tb>>>(w_fc,   p_wf_hi, p_wf_lo, DD, D4);
    wtrans_kernel<<<dim3(DD / 32, D4 / 32), tb>>>(w_out,  p_wo_hi, p_wo_lo, D4, DD);

    ln_kernel<<<ROWS, 256>>>(x, ln1_g, ln1_b, p_xn_hi, p_xn_lo);

    mm_kernel<0><<<dim3(D3 / 128, ROWS / 128), 256, MM_SMEM>>>(
        p_xn_hi, p_xn_lo, p_wa_hi, p_wa_lo, nullptr, p_qkv, nullptr, nullptr,
        ROWS, D3, DD);

    attn_kernel<<<dim3(TT / 64, BB * HH), 256, ATTN_SMEM_BYTES>>>(p_qkv, p_y_hi, p_y_lo);

    mm_kernel<1><<<dim3(DD / 128, ROWS / 128), 256, MM_SMEM>>>(
        p_y_hi, p_y_lo, p_wp_hi, p_wp_lo, x, p_x2, nullptr, nullptr,
        ROWS, DD, DD);

    ln_kernel<<<ROWS, 256>>>(p_x2, ln2_g, ln2_b, p_xn_hi, p_xn_lo);

    mm_kernel<2><<<dim3(D4 / 128, ROWS / 128), 256, MM_SMEM>>>(
        p_xn_hi, p_xn_lo, p_wf_hi, p_wf_lo, nullptr, nullptr, p_fc_hi, p_fc_lo,
        ROWS, D4, DD);

    mm_kernel<1><<<dim3(DD / 128, ROWS / 128), 256, MM_SMEM>>>(
        p_fc_hi, p_fc_lo, p_wo_hi, p_wo_lo, p_x2, out, nullptr, nullptr,
        ROWS, DD, D4);
}

// round 5
// speedup vs baseline: 1.8662x; 1.0447x over previous
#include <cuda_runtime.h>
#include <cuda_bf16.h>
#include <math.h>
#include <stdint.h>

#define BB 2
#define TT 2048
#define DD 1024
#define HH 16
#define HDIM 64
#define ROWS (BB * TT)
#define D3 (3 * DD)
#define D4 (4 * DD)

__device__ float g_x2 [ROWS * DD];

__device__ __nv_bfloat16 g_xn_hi [ROWS * DD], g_xn_lo [ROWS * DD];
__device__ __nv_bfloat16 g_qkv_hi[ROWS * D3], g_qkv_lo[ROWS * D3];
__device__ __nv_bfloat16 g_y_hi  [ROWS * DD], g_y_lo  [ROWS * DD];
__device__ __nv_bfloat16 g_fc_hi [ROWS * D4], g_fc_lo [ROWS * D4];

__device__ __nv_bfloat16 g_wattn_hi[D3 * DD], g_wattn_lo[D3 * DD];
__device__ __nv_bfloat16 g_wproj_hi[DD * DD], g_wproj_lo[DD * DD];
__device__ __nv_bfloat16 g_wfc_hi [D4 * DD], g_wfc_lo [D4 * DD];
__device__ __nv_bfloat16 g_wout_hi[DD * D4], g_wout_lo[DD * D4];

__device__ __forceinline__ uint32_t smem_u32(const void* p) {
    uint32_t a;
    asm("{ .reg .u64 t; cvta.to.shared.u64 t, %1; cvt.u32.u64 %0, t; }"
        : "=r"(a) : "l"(p));
    return a;
}

__device__ __forceinline__ void cp16(uint32_t dst, const void* src) {
    asm volatile("cp.async.cg.shared.global [%0], [%1], 16;"
                 :: "r"(dst), "l"(src));
}
__device__ __forceinline__ void cp_commit() {
    asm volatile("cp.async.commit_group;");
}
__device__ __forceinline__ void cp_wait3() {
    asm volatile("cp.async.wait_group 3;");
}
__device__ __forceinline__ void cp_wait1() {
    asm volatile("cp.async.wait_group 1;");
}

#define LDSM4(d0, d1, d2, d3, addr)                                          \
    asm volatile("ldmatrix.sync.aligned.m8n8.x4.shared.b16 {%0,%1,%2,%3}, [%4];" \
                 : "=r"(d0), "=r"(d1), "=r"(d2), "=r"(d3) : "r"(addr))

#define LDSM4T(d0, d1, d2, d3, addr)                                         \
    asm volatile("ldmatrix.sync.aligned.m8n8.x4.trans.shared.b16 {%0,%1,%2,%3}, [%4];" \
                 : "=r"(d0), "=r"(d1), "=r"(d2), "=r"(d3) : "r"(addr))

#define MMA_BF16(c, a, b)                                                    \
    asm volatile("mma.sync.aligned.m16n8k16.row.col.f32.bf16.bf16.f32 "      \
                 "{%0,%1,%2,%3}, {%4,%5,%6,%7}, {%8,%9}, {%0,%1,%2,%3};"     \
                 : "+f"((c)[0]), "+f"((c)[1]), "+f"((c)[2]), "+f"((c)[3])    \
                 : "r"((a)[0]), "r"((a)[1]), "r"((a)[2]), "r"((a)[3]),       \
                   "r"((b)[0]), "r"((b)[1]))

__device__ __forceinline__ void split_bf16(float v, __nv_bfloat16& h, __nv_bfloat16& l) {
    h = __float2bfloat16(v);
    l = __float2bfloat16(v - __bfloat162float(h));
}

__device__ __forceinline__ uint32_t pack_bf16(__nv_bfloat16 a, __nv_bfloat16 b) {
    __nv_bfloat162 v; v.x = a; v.y = b;
    return *reinterpret_cast<uint32_t*>(&v);
}

__device__ __forceinline__ void store4bf16(__nv_bfloat16* p,
                                           __nv_bfloat16 a, __nv_bfloat16 b,
                                           __nv_bfloat16 c, __nv_bfloat16 d) {
    uint2 u;
    u.x = pack_bf16(a, b);
    u.y = pack_bf16(c, d);
    *reinterpret_cast<uint2*>(p) = u;
}

__device__ __forceinline__ float gelu_exact(float x) {
    return 0.5f * x * (1.0f + erff(x * 0.70710678118654752f));
}

// ---------------------------------------------------------------------------
__global__ void wtrans_kernel(const float* __restrict__ W,
                              __nv_bfloat16* __restrict__ Thi,
                              __nv_bfloat16* __restrict__ Tlo,
                              int K, int N) {
    __shared__ float s[32][33];
    const int n0 = blockIdx.x * 32;
    const int k0 = blockIdx.y * 32;
    const int tx = threadIdx.x, ty = threadIdx.y;
    #pragma unroll
    for (int i = 0; i < 4; i++)
        s[ty + 8 * i][tx] = W[(size_t)(k0 + ty + 8 * i) * N + n0 + tx];
    __syncthreads();
    #pragma unroll
    for (int i = 0; i < 4; i++) {
        const float v = s[tx][ty + 8 * i];
        __nv_bfloat16 h, l;
        split_bf16(v, h, l);
        const size_t o = (size_t)(n0 + ty + 8 * i) * K + k0 + tx;
        Thi[o] = h;
        Tlo[o] = l;
    }
}

// ---------------------------------------------------------------------------
__global__ void ln_kernel(const float* __restrict__ x,
                          const float* __restrict__ g,
                          const float* __restrict__ b,
                          __nv_bfloat16* __restrict__ ohi,
                          __nv_bfloat16* __restrict__ olo) {
    __shared__ float s_sum[8];
    __shared__ float s_sq[8];
    const int row = blockIdx.x;
    const int tid = threadIdx.x;
    const float4* xr = (const float4*)(x + (size_t)row * DD);
    float4 v = xr[tid];
    float s  = v.x + v.y + v.z + v.w;
    float ss = v.x * v.x + v.y * v.y + v.z * v.z + v.w * v.w;
    #pragma unroll
    for (int off = 16; off > 0; off >>= 1) {
        s  += __shfl_xor_sync(0xffffffffu, s,  off);
        ss += __shfl_xor_sync(0xffffffffu, ss, off);
    }
    if ((tid & 31) == 0) { s_sum[tid >> 5] = s; s_sq[tid >> 5] = ss; }
    __syncthreads();
    float ts = 0.f, tss = 0.f;
    #pragma unroll
    for (int i = 0; i < 8; i++) { ts += s_sum[i]; tss += s_sq[i]; }
    const float mean = ts * (1.0f / DD);
    const float var  = tss * (1.0f / DD) - mean * mean;
    const float rstd = rsqrtf(var + 1e-5f);
    float4 gv = ((const float4*)g)[tid];
    float4 bv = ((const float4*)b)[tid];
    float o0 = (v.x - mean) * rstd * gv.x + bv.x;
    float o1 = (v.y - mean) * rstd * gv.y + bv.y;
    float o2 = (v.z - mean) * rstd * gv.z + bv.z;
    float o3 = (v.w - mean) * rstd * gv.w + bv.w;
    __nv_bfloat16 h0, l0, h1, l1, h2, l2, h3, l3;
    split_bf16(o0, h0, l0); split_bf16(o1, h1, l1);
    split_bf16(o2, h2, l2); split_bf16(o3, h3, l3);
    const size_t o = (size_t)row * DD + tid * 4;
    store4bf16(ohi + o, h0, h1, h2, h3);
    store4bf16(olo + o, l0, l1, l2, l3);
}

// ---------------------------------------------------------------------------
#define CHUNK 32
#define ROWB 80
#define ARRB (128 * ROWB)
#define STAGEB (4 * ARRB)
#define NSTAGE 4
#define MM_SMEM (NSTAGE * STAGEB)

template<int EPI>
__global__ void __launch_bounds__(256, 1)
mm_kernel(const __nv_bfloat16* __restrict__ Ahi, const __nv_bfloat16* __restrict__ Alo,
          const __nv_bfloat16* __restrict__ Bhi, const __nv_bfloat16* __restrict__ Blo,
          const float* __restrict__ R, float* __restrict__ C,
          __nv_bfloat16* __restrict__ Chi, __nv_bfloat16* __restrict__ Clo,
          int M, int N, int K) {
    extern __shared__ char smem[];
    const uint32_t sbase = smem_u32(smem);

    const int tid  = threadIdx.x;
    const int lane = tid & 31;
    const int wid  = tid >> 5;
    const int wm   = wid & 3;
    const int wn   = wid >> 2;
    const int row0 = blockIdx.y * 128;
    const int col0 = blockIdx.x * 128;

    const int i0r = tid >> 2, i0c = tid & 3;
    const int i1r = (tid + 256) >> 2, i1c = tid & 3;

    const int nch = K >> 5;

    float acc[2][8][4];
    #pragma unroll
    for (int mi = 0; mi < 2; mi++)
        #pragma unroll
        for (int ni = 0; ni < 8; ni++)
            #pragma unroll
            for (int j = 0; j < 4; j++) acc[mi][ni][j] = 0.f;

    const uint32_t a_off = (uint32_t)((wm * 32 + (lane & 15)) * ROWB + ((lane >> 4) << 4));
    const uint32_t b_off = (uint32_t)((wn * 64 + ((lane >> 4) << 3) + (lane & 7)) * ROWB
                                      + (((lane >> 3) & 1) << 4));

#define ISSUE(ch)                                                             \
    do {                                                                      \
        const int k0_ = (ch) * CHUNK;                                         \
        const uint32_t sb_ = sbase + ((ch) % NSTAGE) * STAGEB;                \
        cp16(sb_ + 0*ARRB + i0r*ROWB + i0c*16, Ahi + (size_t)(row0+i0r)*K + k0_ + i0c*8); \
        cp16(sb_ + 0*ARRB + i1r*ROWB + i1c*16, Ahi + (size_t)(row0+i1r)*K + k0_ + i1c*8); \
        cp16(sb_ + 1*ARRB + i0r*ROWB + i0c*16, Alo + (size_t)(row0+i0r)*K + k0_ + i0c*8); \
        cp16(sb_ + 1*ARRB + i1r*ROWB + i1c*16, Alo + (size_t)(row0+i1r)*K + k0_ + i1c*8); \
        cp16(sb_ + 2*ARRB + i0r*ROWB + i0c*16, Bhi + (size_t)(col0+i0r)*K + k0_ + i0c*8); \
        cp16(sb_ + 2*ARRB + i1r*ROWB + i1c*16, Bhi + (size_t)(col0+i1r)*K + k0_ + i1c*8); \
        cp16(sb_ + 3*ARRB + i0r*ROWB + i0c*16, Blo + (size_t)(col0+i0r)*K + k0_ + i0c*8); \
        cp16(sb_ + 3*ARRB + i1r*ROWB + i1c*16, Blo + (size_t)(col0+i1r)*K + k0_ + i1c*8); \
    } while (0)

    ISSUE(0); cp_commit();
    ISSUE(1); cp_commit();
    ISSUE(2); cp_commit();

    for (int c = 0; c < nch; c++) {
        if (c + 3 < nch) ISSUE(c + 3);
        cp_commit();
        cp_wait3();
        __syncthreads();

        const uint32_t sb = sbase + (c % NSTAGE) * STAGEB;
        #pragma unroll
        for (int ks = 0; ks < 2; ks++) {
            uint32_t ah[2][4], al[2][4], bh[8][2], bl[8][2];
            #pragma unroll
            for (int mi = 0; mi < 2; mi++) {
                const uint32_t aa = sb + a_off + mi * (16 * ROWB) + ks * 32;
                LDSM4(ah[mi][0], ah[mi][1], ah[mi][2], ah[mi][3], aa);
                LDSM4(al[mi][0], al[mi][1], al[mi][2], al[mi][3], aa + ARRB);
            }
            #pragma unroll
            for (int nb = 0; nb < 4; nb++) {
                const uint32_t ba = sb + 2 * ARRB + b_off + nb * (16 * ROWB) + ks * 32;
                LDSM4(bh[2*nb][0], bh[2*nb][1], bh[2*nb+1][0], bh[2*nb+1][1], ba);
                LDSM4(bl[2*nb][0], bl[2*nb][1], bl[2*nb+1][0], bl[2*nb+1][1], ba + ARRB);
            }
            #pragma unroll
            for (int mi = 0; mi < 2; mi++)
                #pragma unroll
                for (int ni = 0; ni < 8; ni++) {
                    MMA_BF16(acc[mi][ni], ah[mi], bh[ni]);
                    MMA_BF16(acc[mi][ni], ah[mi], bl[ni]);
                    MMA_BF16(acc[mi][ni], al[mi], bh[ni]);
                }
        }
        __syncthreads();
    }

#undef ISSUE

    const int r_b = row0 + wm * 32 + (lane >> 2);
    const int c_b = col0 + wn * 64 + (lane & 3) * 2;
    #pragma unroll
    for (int mi = 0; mi < 2; mi++) {
        #pragma unroll
        for (int half = 0; half < 2; half++) {
            const size_t r = (size_t)(r_b + mi * 16 + half * 8);
            #pragma unroll
            for (int ni = 0; ni < 8; ni++) {
                const int col = c_b + ni * 8;
                float v0 = acc[mi][ni][half * 2 + 0];
                float v1 = acc[mi][ni][half * 2 + 1];
                if (EPI == 0 || EPI == 1) {
                    if (EPI == 1) {
                        const float2 rv = *(const float2*)(R + r * N + col);
                        v0 += rv.x; v1 += rv.y;
                    }
                    float2 o; o.x = v0; o.y = v1;
                    *(float2*)(C + r * N + col) = o;
                } else {
                    if (EPI == 2) { v0 = gelu_exact(v0); v1 = gelu_exact(v1); }
                    __nv_bfloat16 h0, l0, h1, l1;
                    split_bf16(v0, h0, l0);
                    split_bf16(v1, h1, l1);
                    *(uint32_t*)(Chi + r * N + col) = pack_bf16(h0, h1);
                    *(uint32_t*)(Clo + r * N + col) = pack_bf16(l0, l1);
                }
            }
        }
    }
}

// ---------------------------------------------------------------------------
// Tensor-core causal flash attention (bf16 hi/lo split).
// ---------------------------------------------------------------------------
#define AROWB 144
#define AARR  (64 * AROWB)
#define ATT_SMEM (10 * AARR)

__global__ void __launch_bounds__(128, 2)
attn_kernel(const __nv_bfloat16* __restrict__ qkv_hi,
            const __nv_bfloat16* __restrict__ qkv_lo,
            __nv_bfloat16* __restrict__ yhi,
            __nv_bfloat16* __restrict__ ylo) {
    extern __shared__ char asmem[];
    const uint32_t sb = smem_u32(asmem);

    const int qt = (int)gridDim.x - 1 - (int)blockIdx.x;
    const int bh = blockIdx.y;
    const int bb = bh >> 4;
    const int hh = bh & 15;

    const int tid  = threadIdx.x;
    const int lane = tid & 31;
    const int w    = tid >> 5;

    const size_t base = (size_t)bb * TT * D3 + hh * HDIM;
    const __nv_bfloat16* qh = qkv_hi + base;
    const __nv_bfloat16* ql = qkv_lo + base;
    const __nv_bfloat16* kh = qkv_hi + base + DD;
    const __nv_bfloat16* kl = qkv_lo + base + DD;
    const __nv_bfloat16* vh = qkv_hi + base + 2 * DD;
    const __nv_bfloat16* vl = qkv_lo + base + 2 * DD;

    const uint32_t sQh = sb;
    const uint32_t sQl = sb + AARR;
    const int nkt = qt + 1;

#define ALOAD(dst, src, trow)                                                 \
    do {                                                                      \
        _Pragma("unroll")                                                     \
        for (int i_ = 0; i_ < 4; i_++) {                                      \
            const int idx_ = tid + i_ * 128;                                  \
            const int r_ = idx_ >> 3, c_ = idx_ & 7;                          \
            cp16((dst) + r_ * AROWB + c_ * 16,                                \
                 (src) + (size_t)((trow) + r_) * D3 + c_ * 8);                \
        }                                                                     \
    } while (0)

#define AKV(kt_)                                                              \
    do {                                                                      \
        const uint32_t st_ = sb + 2 * AARR + ((kt_) & 1) * (4 * AARR);        \
        ALOAD(st_ + 0 * AARR, kh, (kt_) * 64);                                \
        ALOAD(st_ + 1 * AARR, kl, (kt_) * 64);                                \
        ALOAD(st_ + 2 * AARR, vh, (kt_) * 64);                                \
        ALOAD(st_ + 3 * AARR, vl, (kt_) * 64);                                \
    } while (0)

    ALOAD(sQh, qh, qt * 64);
    ALOAD(sQl, ql, qt * 64);
    AKV(0);
    cp_commit();
    if (nkt > 1) AKV(1);
    cp_commit();
    cp_wait1();
    __syncthreads();

    uint32_t qfh[4][4], qfl[4][4];
    {
        const uint32_t qa = (uint32_t)((w * 16 + (lane & 15)) * AROWB + ((lane >> 4) << 4));
        #pragma unroll
        for (int ks = 0; ks < 4; ks++) {
            LDSM4(qfh[ks][0], qfh[ks][1], qfh[ks][2], qfh[ks][3], sQh + qa + ks * 32);
            LDSM4(qfl[ks][0], qfl[ks][1], qfl[ks][2], qfl[ks][3], sQl + qa + ks * 32);
        }
    }

    float o[8][4];
    #pragma unroll
    for (int nb = 0; nb < 8; nb++)
        #pragma unroll
        for (int j = 0; j < 4; j++) o[nb][j] = 0.f;
    float m0 = -INFINITY, m1 = -INFINITY, l0 = 0.f, l1 = 0.f;

    const uint32_t kb_off = (uint32_t)((((lane >> 4) << 3) + (lane & 7)) * AROWB
                                       + (((lane >> 3) & 1) << 4));
    const uint32_t vb_off = (uint32_t)(((((lane >> 3) & 1) << 3) + (lane & 7)) * AROWB
                                       + ((lane >> 4) << 4));

    for (int kt = 0; kt < nkt; kt++) {
        const uint32_t stg = sb + 2 * AARR + (kt & 1) * (4 * AARR);

        float s[8][4];
        #pragma unroll
        for (int nb = 0; nb < 8; nb++)
            #pragma unroll
            for (int j = 0; j < 4; j++) s[nb][j] = 0.f;

        #pragma unroll
        for (int ks = 0; ks < 4; ks++) {
            uint32_t bhk[8][2], blk[8][2];
            #pragma unroll
            for (int nb2 = 0; nb2 < 4; nb2++) {
                const uint32_t ka = stg + kb_off + nb2 * (16 * AROWB) + ks * 32;
                LDSM4(bhk[2*nb2][0], bhk[2*nb2][1], bhk[2*nb2+1][0], bhk[2*nb2+1][1], ka);
                LDSM4(blk[2*nb2][0], blk[2*nb2][1], blk[2*nb2+1][0], blk[2*nb2+1][1], ka + AARR);
            }
            #pragma unroll
            for (int nb = 0; nb < 8; nb++) {
                MMA_BF16(s[nb], qfh[ks], bhk[nb]);
                MMA_BF16(s[nb], qfh[ks], blk[nb]);
                MMA_BF16(s[nb], qfl[ks], bhk[nb]);
            }
        }

        #pragma unroll
        for (int nb = 0; nb < 8; nb++)
            #pragma unroll
            for (int j = 0; j < 4; j++) s[nb][j] *= 0.125f;

        if (kt == qt) {
            const int r0 = w * 16 + (lane >> 2);
            #pragma unroll
            for (int nb = 0; nb < 8; nb++) {
                const int c0 = nb * 8 + (lane & 3) * 2;
                if (c0     > r0)     s[nb][0] = -1e30f;
                if (c0 + 1 > r0)     s[nb][1] = -1e30f;
                if (c0     > r0 + 8) s[nb][2] = -1e30f;
                if (c0 + 1 > r0 + 8) s[nb][3] = -1e30f;
            }
        }

        float mx0 = -INFINITY, mx1 = -INFINITY;
        #pragma unroll
        for (int nb = 0; nb < 8; nb++) {
            mx0 = fmaxf(mx0, fmaxf(s[nb][0], s[nb][1]));
            mx1 = fmaxf(mx1, fmaxf(s[nb][2], s[nb][3]));
        }
        mx0 = fmaxf(mx0, __shfl_xor_sync(0xffffffffu, mx0, 1));
        mx0 = fmaxf(mx0, __shfl_xor_sync(0xffffffffu, mx0, 2));
        mx1 = fmaxf(mx1, __shfl_xor_sync(0xffffffffu, mx1, 1));
        mx1 = fmaxf(mx1, __shfl_xor_sync(0xffffffffu, mx1, 2));

        const float mn0 = fmaxf(m0, mx0);
        const float mn1 = fmaxf(m1, mx1);
        const float al0 = __expf(m0 - mn0);
        const float al1 = __expf(m1 - mn1);
        m0 = mn0; m1 = mn1;

        float ls0 = 0.f, ls1 = 0.f;
        #pragma unroll
        for (int nb = 0; nb < 8; nb++) {
            s[nb][0] = __expf(s[nb][0] - mn0);
            s[nb][1] = __expf(s[nb][1] - mn0);
            s[nb][2] = __expf(s[nb][2] - mn1);
            s[nb][3] = __expf(s[nb][3] - mn1);
            ls0 += s[nb][0] + s[nb][1];
            ls1 += s[nb][2] + s[nb][3];
        }
        ls0 += __shfl_xor_sync(0xffffffffu, ls0, 1);
        ls0 += __shfl_xor_sync(0xffffffffu, ls0, 2);
        ls1 += __shfl_xor_sync(0xffffffffu, ls1, 1);
        ls1 += __shfl_xor_sync(0xffffffffu, ls1, 2);
        l0 = l0 * al0 + ls0;
        l1 = l1 * al1 + ls1;

        #pragma unroll
        for (int nb = 0; nb < 8; nb++) {
            o[nb][0] *= al0; o[nb][1] *= al0;
            o[nb][2] *= al1; o[nb][3] *= al1;
        }

        uint32_t pfh[4][4], pfl[4][4];
        #pragma unroll
        for (int t = 0; t < 4; t++) {
            __nv_bfloat16 h[8], lo_[8];
            #pragma unroll
            for (int j = 0; j < 4; j++) {
                split_bf16(s[2*t][j],   h[j],     lo_[j]);
                split_bf16(s[2*t+1][j], h[4 + j], lo_[4 + j]);
            }
            pfh[t][0] = pack_bf16(h[0], h[1]);
            pfh[t][1] = pack_bf16(h[2], h[3]);
            pfh[t][2] = pack_bf16(h[4], h[5]);
            pfh[t][3] = pack_bf16(h[6], h[7]);
            pfl[t][0] = pack_bf16(lo_[0], lo_[1]);
            pfl[t][1] = pack_bf16(lo_[2], lo_[3]);
            pfl[t][2] = pack_bf16(lo_[4], lo_[5]);
            pfl[t][3] = pack_bf16(lo_[6], lo_[7]);
        }

        const uint32_t vbase = stg + 2 * AARR;
        #pragma unroll
        for (int t = 0; t < 4; t++) {
            uint32_t bvh[8][2], bvl[8][2];
            #pragma unroll
            for (int j2 = 0; j2 < 4; j2++) {
                const uint32_t va = vbase + vb_off + t * (16 * AROWB) + j2 * 32;
                LDSM4T(bvh[2*j2][0], bvh[2*j2][1], bvh[2*j2+1][0], bvh[2*j2+1][1], va);
                LDSM4T(bvl[2*j2][0], bvl[2*j2][1], bvl[2*j2+1][0], bvl[2*j2+1][1], va + AARR);
            }
            #pragma unroll
            for (int nb = 0; nb < 8; nb++) {
                MMA_BF16(o[nb], pfh[t], bvh[nb]);
                MMA_BF16(o[nb], pfh[t], bvl[nb]);
                MMA_BF16(o[nb], pfl[t], bvh[nb]);
            }
        }

        __syncthreads();
        if (kt + 2 < nkt) AKV(kt + 2);
        cp_commit();
        cp_wait1();
        __syncthreads();
    }

#undef AKV
#undef ALOAD

    const float inv0 = 1.0f / l0;
    const float inv1 = 1.0f / l1;
    const int rr0 = qt * 64 + w * 16 + (lane >> 2);
    #pragma unroll
    for (int nb = 0; nb < 8; nb++) {
        const int col = hh * HDIM + nb * 8 + (lane & 3) * 2;
        const size_t t0 = (size_t)(bb * TT + rr0) * DD + col;
        const size_t t1 = (size_t)(bb * TT + rr0 + 8) * DD + col;
        __nv_bfloat16 h0, lo0, h1, lo1;
        split_bf16(o[nb][0] * inv0, h0, lo0);
        split_bf16(o[nb][1] * inv0, h1, lo1);
        *(uint32_t*)(yhi + t0) = pack_bf16(h0, h1);
        *(uint32_t*)(ylo + t0) = pack_bf16(lo0, lo1);
        split_bf16(o[nb][2] * inv1, h0, lo0);
        split_bf16(o[nb][3] * inv1, h1, lo1);
        *(uint32_t*)(yhi + t1) = pack_bf16(h0, h1);
        *(uint32_t*)(ylo + t1) = pack_bf16(lo0, lo1);
    }
}

// ---------------------------------------------------------------------------
extern "C" void kernel_launch(void* const* d_in, const int* in_sizes, int n_in,
                              void* d_out, int out_size) {
    const float* x      = (const float*)d_in[0];
    const float* w_attn = (const float*)d_in[1];
    const float* w_proj = (const float*)d_in[2];
    const float* w_fc   = (const float*)d_in[3];
    const float* w_out  = (const float*)d_in[4];
    const float* ln1_g  = (const float*)d_in[5];
    const float* ln1_b  = (const float*)d_in[6];
    const float* ln2_g  = (const float*)d_in[7];
    const float* ln2_b  = (const float*)d_in[8];
    float* out = (float*)d_out;

    float* p_x2;
    __nv_bfloat16 *p_xn_hi, *p_xn_lo, *p_qkv_hi, *p_qkv_lo;
    __nv_bfloat16 *p_y_hi, *p_y_lo, *p_fc_hi, *p_fc_lo;
    __nv_bfloat16 *p_wa_hi, *p_wa_lo, *p_wp_hi, *p_wp_lo;
    __nv_bfloat16 *p_wf_hi, *p_wf_lo, *p_wo_hi, *p_wo_lo;
    cudaGetSymbolAddress((void**)&p_x2,     g_x2);
    cudaGetSymbolAddress((void**)&p_xn_hi,  g_xn_hi);
    cudaGetSymbolAddress((void**)&p_xn_lo,  g_xn_lo);
    cudaGetSymbolAddress((void**)&p_qkv_hi, g_qkv_hi);
    cudaGetSymbolAddress((void**)&p_qkv_lo, g_qkv_lo);
    cudaGetSymbolAddress((void**)&p_y_hi,   g_y_hi);
    cudaGetSymbolAddress((void**)&p_y_lo,   g_y_lo);
    cudaGetSymbolAddress((void**)&p_fc_hi,  g_fc_hi);
    cudaGetSymbolAddress((void**)&p_fc_lo,  g_fc_lo);
    cudaGetSymbolAddress((void**)&p_wa_hi,  g_wattn_hi);
    cudaGetSymbolAddress((void**)&p_wa_lo,  g_wattn_lo);
    cudaGetSymbolAddress((void**)&p_wp_hi,  g_wproj_hi);
    cudaGetSymbolAddress((void**)&p_wp_lo,  g_wproj_lo);
    cudaGetSymbolAddress((void**)&p_wf_hi,  g_wfc_hi);
    cudaGetSymbolAddress((void**)&p_wf_lo,  g_wfc_lo);
    cudaGetSymbolAddress((void**)&p_wo_hi,  g_wout_hi);
    cudaGetSymbolAddress((void**)&p_wo_lo,  g_wout_lo);

    cudaFuncSetAttribute(attn_kernel,
                         cudaFuncAttributeMaxDynamicSharedMemorySize, ATT_SMEM);
    cudaFuncSetAttribute(mm_kernel<1>,
                         cudaFuncAttributeMaxDynamicSharedMemorySize, MM_SMEM);
    cudaFuncSetAttribute(mm_kernel<2>,
                         cudaFuncAttributeMaxDynamicSharedMemorySize, MM_SMEM);
    cudaFuncSetAttribute(mm_kernel<3>,
                         cudaFuncAttributeMaxDynamicSharedMemorySize, MM_SMEM);

    const dim3 tb(32, 8);

    wtrans_kernel<<<dim3(D3 / 32, DD / 32), tb>>>(w_attn, p_wa_hi, p_wa_lo, DD, D3);
    wtrans_kernel<<<dim3(DD / 32, DD / 32), tb>>>(w_proj, p_wp_hi, p_wp_lo, DD, DD);
    wtrans_kernel<<<dim3(D4 / 32, DD / 32), tb>>>(w_fc,   p_wf_hi, p_wf_lo, DD, D4);
    wtrans_kernel<<<dim3(DD / 32, D4 / 32), tb>>>(w_out,  p_wo_hi, p_wo_lo, D4, DD);

    ln_kernel<<<ROWS, 256>>>(x, ln1_g, ln1_b, p_xn_hi, p_xn_lo);

    mm_kernel<3><<<dim3(D3 / 128, ROWS / 128), 256, MM_SMEM>>>(
        p_xn_hi, p_xn_lo, p_wa_hi, p_wa_lo, nullptr, nullptr, p_qkv_hi, p_qkv_lo,
        ROWS, D3, DD);

    attn_kernel<<<dim3(TT / 64, BB * HH), 128, ATT_SMEM>>>(
        p_qkv_hi, p_qkv_lo, p_y_hi, p_y_lo);

    mm_kernel<1><<<dim3(DD / 128, ROWS / 128), 256, MM_SMEM>>>(
        p_y_hi, p_y_lo, p_wp_hi, p_wp_lo, x, p_x2, nullptr, nullptr,
        ROWS, DD, DD);

    ln_kernel<<<ROWS, 256>>>(p_x2, ln2_g, ln2_b, p_xn_hi, p_xn_lo);

    mm_kernel<2><<<dim3(D4 / 128, ROWS / 128), 256, MM_SMEM>>>(
        p_xn_hi, p_xn_lo, p_wf_hi, p_wf_lo, nullptr, nullptr, p_fc_hi, p_fc_lo,
        ROWS, D4, DD);

    mm_kernel<1><<<dim3(DD / 128, ROWS / 128), 256, MM_SMEM>>>(
        p_fc_hi, p_fc_lo, p_wo_hi, p_wo_lo, p_x2, out, nullptr, nullptr,
        ROWS, DD, D4);
}

// round 6
// speedup vs baseline: 3.3251x; 1.7818x over previous
#include <cuda_runtime.h>
#include <cuda_bf16.h>
#include <math.h>
#include <stdint.h>

#define BB 2
#define TT 2048
#define DD 1024
#define HH 16
#define HDIM 64
#define ROWS (BB * TT)
#define D3 (3 * DD)
#define D4 (4 * DD)

__device__ float g_x2 [ROWS * DD];

__device__ __nv_bfloat16 g_xn_hi [ROWS * DD], g_xn_lo [ROWS * DD];
__device__ __nv_bfloat16 g_qkv_hi[ROWS * D3], g_qkv_lo[ROWS * D3];
__device__ __nv_bfloat16 g_y_hi  [ROWS * DD], g_y_lo  [ROWS * DD];
__device__ __nv_bfloat16 g_fc_hi [ROWS * D4], g_fc_lo [ROWS * D4];

__device__ __nv_bfloat16 g_wattn_hi[D3 * DD], g_wattn_lo[D3 * DD];
__device__ __nv_bfloat16 g_wproj_hi[DD * DD], g_wproj_lo[DD * DD];
__device__ __nv_bfloat16 g_wfc_hi [D4 * DD], g_wfc_lo [D4 * DD];
__device__ __nv_bfloat16 g_wout_hi[DD * D4], g_wout_lo[DD * D4];

__device__ __forceinline__ uint32_t smem_u32(const void* p) {
    uint32_t a;
    asm("{ .reg .u64 t; cvta.to.shared.u64 t, %1; cvt.u32.u64 %0, t; }"
        : "=r"(a) : "l"(p));
    return a;
}

__device__ __forceinline__ void cp16(uint32_t dst, const void* src) {
    asm volatile("cp.async.cg.shared.global [%0], [%1], 16;"
                 :: "r"(dst), "l"(src));
}
__device__ __forceinline__ void cp_commit() {
    asm volatile("cp.async.commit_group;");
}
__device__ __forceinline__ void cp_wait1() {
    asm volatile("cp.async.wait_group 1;");
}

#define LDSM4(d0, d1, d2, d3, addr)                                          \
    asm volatile("ldmatrix.sync.aligned.m8n8.x4.shared.b16 {%0,%1,%2,%3}, [%4];" \
                 : "=r"(d0), "=r"(d1), "=r"(d2), "=r"(d3) : "r"(addr))

#define LDSM4T(d0, d1, d2, d3, addr)                                         \
    asm volatile("ldmatrix.sync.aligned.m8n8.x4.trans.shared.b16 {%0,%1,%2,%3}, [%4];" \
                 : "=r"(d0), "=r"(d1), "=r"(d2), "=r"(d3) : "r"(addr))

#define MMA_BF16(c, a, b)                                                    \
    asm volatile("mma.sync.aligned.m16n8k16.row.col.f32.bf16.bf16.f32 "      \
                 "{%0,%1,%2,%3}, {%4,%5,%6,%7}, {%8,%9}, {%0,%1,%2,%3};"     \
                 : "+f"((c)[0]), "+f"((c)[1]), "+f"((c)[2]), "+f"((c)[3])    \
                 : "r"((a)[0]), "r"((a)[1]), "r"((a)[2]), "r"((a)[3]),       \
                   "r"((b)[0]), "r"((b)[1]))

__device__ __forceinline__ void split_bf16(float v, __nv_bfloat16& h, __nv_bfloat16& l) {
    h = __float2bfloat16(v);
    l = __float2bfloat16(v - __bfloat162float(h));
}

__device__ __forceinline__ uint32_t pack_bf16(__nv_bfloat16 a, __nv_bfloat16 b) {
    __nv_bfloat162 v; v.x = a; v.y = b;
    return *reinterpret_cast<uint32_t*>(&v);
}

__device__ __forceinline__ void store4bf16(__nv_bfloat16* p,
                                           __nv_bfloat16 a, __nv_bfloat16 b,
                                           __nv_bfloat16 c, __nv_bfloat16 d) {
    uint2 u;
    u.x = pack_bf16(a, b);
    u.y = pack_bf16(c, d);
    *reinterpret_cast<uint2*>(p) = u;
}

__device__ __forceinline__ float gelu_exact(float x) {
    return 0.5f * x * (1.0f + erff(x * 0.70710678118654752f));
}

// ---------------------------------------------------------------------------
__global__ void wtrans_kernel(const float* __restrict__ W,
                              __nv_bfloat16* __restrict__ Thi,
                              __nv_bfloat16* __restrict__ Tlo,
                              int K, int N) {
    __shared__ float s[32][33];
    const int n0 = blockIdx.x * 32;
    const int k0 = blockIdx.y * 32;
    const int tx = threadIdx.x, ty = threadIdx.y;
    #pragma unroll
    for (int i = 0; i < 4; i++)
        s[ty + 8 * i][tx] = W[(size_t)(k0 + ty + 8 * i) * N + n0 + tx];
    __syncthreads();
    #pragma unroll
    for (int i = 0; i < 4; i++) {
        const float v = s[tx][ty + 8 * i];
        __nv_bfloat16 h, l;
        split_bf16(v, h, l);
        const size_t o = (size_t)(n0 + ty + 8 * i) * K + k0 + tx;
        Thi[o] = h;
        Tlo[o] = l;
    }
}

// ---------------------------------------------------------------------------
__global__ void ln_kernel(const float* __restrict__ x,
                          const float* __restrict__ g,
                          const float* __restrict__ b,
                          __nv_bfloat16* __restrict__ ohi,
                          __nv_bfloat16* __restrict__ olo) {
    __shared__ float s_sum[8];
    __shared__ float s_sq[8];
    const int row = blockIdx.x;
    const int tid = threadIdx.x;
    const float4* xr = (const float4*)(x + (size_t)row * DD);
    float4 v = xr[tid];
    float s  = v.x + v.y + v.z + v.w;
    float ss = v.x * v.x + v.y * v.y + v.z * v.z + v.w * v.w;
    #pragma unroll
    for (int off = 16; off > 0; off >>= 1) {
        s  += __shfl_xor_sync(0xffffffffu, s,  off);
        ss += __shfl_xor_sync(0xffffffffu, ss, off);
    }
    if ((tid & 31) == 0) { s_sum[tid >> 5] = s; s_sq[tid >> 5] = ss; }
    __syncthreads();
    float ts = 0.f, tss = 0.f;
    #pragma unroll
    for (int i = 0; i < 8; i++) { ts += s_sum[i]; tss += s_sq[i]; }
    const float mean = ts * (1.0f / DD);
    const float var  = tss * (1.0f / DD) - mean * mean;
    const float rstd = rsqrtf(var + 1e-5f);
    float4 gv = ((const float4*)g)[tid];
    float4 bv = ((const float4*)b)[tid];
    float o0 = (v.x - mean) * rstd * gv.x + bv.x;
    float o1 = (v.y - mean) * rstd * gv.y + bv.y;
    float o2 = (v.z - mean) * rstd * gv.z + bv.z;
    float o3 = (v.w - mean) * rstd * gv.w + bv.w;
    __nv_bfloat16 h0, l0, h1, l1, h2, l2, h3, l3;
    split_bf16(o0, h0, l0); split_bf16(o1, h1, l1);
    split_bf16(o2, h2, l2); split_bf16(o3, h3, l3);
    const size_t o = (size_t)row * DD + tid * 4;
    store4bf16(ohi + o, h0, h1, h2, h3);
    store4bf16(olo + o, l0, l1, l2, l3);
}

// ---------------------------------------------------------------------------
// bf16-split GEMM, 2-stage double buffer, 2 CTAs/SM.
// ---------------------------------------------------------------------------
#define CHUNK 32
#define ROWB 80
#define ARRB (128 * ROWB)
#define STAGEB (4 * ARRB)
#define NSTAGE 2
#define MM_SMEM (NSTAGE * STAGEB)    // 81920

template<int EPI>
__global__ void __launch_bounds__(256, 2)
mm_kernel(const __nv_bfloat16* __restrict__ Ahi, const __nv_bfloat16* __restrict__ Alo,
          const __nv_bfloat16* __restrict__ Bhi, const __nv_bfloat16* __restrict__ Blo,
          const float* __restrict__ R, float* __restrict__ C,
          __nv_bfloat16* __restrict__ Chi, __nv_bfloat16* __restrict__ Clo,
          int M, int N, int K) {
    extern __shared__ char smem[];
    const uint32_t sbase = smem_u32(smem);

    const int tid  = threadIdx.x;
    const int lane = tid & 31;
    const int wid  = tid >> 5;
    const int wm   = wid & 3;
    const int wn   = wid >> 2;
    const int row0 = blockIdx.y * 128;
    const int col0 = blockIdx.x * 128;

    const int i0r = tid >> 2, i0c = tid & 3;
    const int i1r = (tid + 256) >> 2, i1c = tid & 3;

    const int nch = K >> 5;

    float acc[2][8][4];
    #pragma unroll
    for (int mi = 0; mi < 2; mi++)
        #pragma unroll
        for (int ni = 0; ni < 8; ni++)
            #pragma unroll
            for (int j = 0; j < 4; j++) acc[mi][ni][j] = 0.f;

    const uint32_t a_off = (uint32_t)((wm * 32 + (lane & 15)) * ROWB + ((lane >> 4) << 4));
    const uint32_t b_off = (uint32_t)((wn * 64 + ((lane >> 4) << 3) + (lane & 7)) * ROWB
                                      + (((lane >> 3) & 1) << 4));

#define ISSUE(ch)                                                             \
    do {                                                                      \
        const int k0_ = (ch) * CHUNK;                                         \
        const uint32_t sb_ = sbase + ((ch) & 1) * STAGEB;                     \
        cp16(sb_ + 0*ARRB + i0r*ROWB + i0c*16, Ahi + (size_t)(row0+i0r)*K + k0_ + i0c*8); \
        cp16(sb_ + 0*ARRB + i1r*ROWB + i1c*16, Ahi + (size_t)(row0+i1r)*K + k0_ + i1c*8); \
        cp16(sb_ + 1*ARRB + i0r*ROWB + i0c*16, Alo + (size_t)(row0+i0r)*K + k0_ + i0c*8); \
        cp16(sb_ + 1*ARRB + i1r*ROWB + i1c*16, Alo + (size_t)(row0+i1r)*K + k0_ + i1c*8); \
        cp16(sb_ + 2*ARRB + i0r*ROWB + i0c*16, Bhi + (size_t)(col0+i0r)*K + k0_ + i0c*8); \
        cp16(sb_ + 2*ARRB + i1r*ROWB + i1c*16, Bhi + (size_t)(col0+i1r)*K + k0_ + i1c*8); \
        cp16(sb_ + 3*ARRB + i0r*ROWB + i0c*16, Blo + (size_t)(col0+i0r)*K + k0_ + i0c*8); \
        cp16(sb_ + 3*ARRB + i1r*ROWB + i1c*16, Blo + (size_t)(col0+i1r)*K + k0_ + i1c*8); \
    } while (0)

    ISSUE(0); cp_commit();
    ISSUE(1); cp_commit();

    for (int c = 0; c < nch; c++) {
        cp_wait1();
        __syncthreads();

        const uint32_t sb = sbase + (c & 1) * STAGEB;
        #pragma unroll
        for (int ks = 0; ks < 2; ks++) {
            uint32_t ah[2][4], al[2][4];
            #pragma unroll
            for (int mi = 0; mi < 2; mi++) {
                const uint32_t aa = sb + a_off + mi * (16 * ROWB) + ks * 32;
                LDSM4(ah[mi][0], ah[mi][1], ah[mi][2], ah[mi][3], aa);
                LDSM4(al[mi][0], al[mi][1], al[mi][2], al[mi][3], aa + ARRB);
            }
            #pragma unroll
            for (int nb = 0; nb < 4; nb++) {
                uint32_t bh[2][2], bl[2][2];
                const uint32_t ba = sb + 2 * ARRB + b_off + nb * (16 * ROWB) + ks * 32;
                LDSM4(bh[0][0], bh[0][1], bh[1][0], bh[1][1], ba);
                LDSM4(bl[0][0], bl[0][1], bl[1][0], bl[1][1], ba + ARRB);
                #pragma unroll
                for (int mi = 0; mi < 2; mi++)
                    #pragma unroll
                    for (int q = 0; q < 2; q++) {
                        const int ni = 2 * nb + q;
                        MMA_BF16(acc[mi][ni], ah[mi], bh[q]);
                        MMA_BF16(acc[mi][ni], ah[mi], bl[q]);
                        MMA_BF16(acc[mi][ni], al[mi], bh[q]);
                    }
            }
        }
        __syncthreads();
        if (c + 2 < nch) ISSUE(c + 2);
        cp_commit();
    }

#undef ISSUE

    const int r_b = row0 + wm * 32 + (lane >> 2);
    const int c_b = col0 + wn * 64 + (lane & 3) * 2;
    #pragma unroll
    for (int mi = 0; mi < 2; mi++) {
        #pragma unroll
        for (int half = 0; half < 2; half++) {
            const size_t r = (size_t)(r_b + mi * 16 + half * 8);
            #pragma unroll
            for (int ni = 0; ni < 8; ni++) {
                const int col = c_b + ni * 8;
                float v0 = acc[mi][ni][half * 2 + 0];
                float v1 = acc[mi][ni][half * 2 + 1];
                if (EPI == 0 || EPI == 1) {
                    if (EPI == 1) {
                        const float2 rv = *(const float2*)(R + r * N + col);
                        v0 += rv.x; v1 += rv.y;
                    }
                    float2 o; o.x = v0; o.y = v1;
                    *(float2*)(C + r * N + col) = o;
                } else {
                    if (EPI == 2) { v0 = gelu_exact(v0); v1 = gelu_exact(v1); }
                    __nv_bfloat16 h0, l0, h1, l1;
                    split_bf16(v0, h0, l0);
                    split_bf16(v1, h1, l1);
                    *(uint32_t*)(Chi + r * N + col) = pack_bf16(h0, h1);
                    *(uint32_t*)(Clo + r * N + col) = pack_bf16(l0, l1);
                }
            }
        }
    }
}

// ---------------------------------------------------------------------------
// Tensor-core causal flash attention (bf16 hi/lo split).
// ---------------------------------------------------------------------------
#define AROWB 144
#define AARR  (64 * AROWB)
#define ATT_SMEM (10 * AARR)

__global__ void __launch_bounds__(128, 2)
attn_kernel(const __nv_bfloat16* __restrict__ qkv_hi,
            const __nv_bfloat16* __restrict__ qkv_lo,
            __nv_bfloat16* __restrict__ yhi,
            __nv_bfloat16* __restrict__ ylo) {
    extern __shared__ char asmem[];
    const uint32_t sb = smem_u32(asmem);

    const int qt = (int)gridDim.x - 1 - (int)blockIdx.x;
    const int bh = blockIdx.y;
    const int bb = bh >> 4;
    const int hh = bh & 15;

    const int tid  = threadIdx.x;
    const int lane = tid & 31;
    const int w    = tid >> 5;

    const size_t base = (size_t)bb * TT * D3 + hh * HDIM;
    const __nv_bfloat16* qh = qkv_hi + base;
    const __nv_bfloat16* ql = qkv_lo + base;
    const __nv_bfloat16* kh = qkv_hi + base + DD;
    const __nv_bfloat16* kl = qkv_lo + base + DD;
    const __nv_bfloat16* vh = qkv_hi + base + 2 * DD;
    const __nv_bfloat16* vl = qkv_lo + base + 2 * DD;

    const uint32_t sQh = sb;
    const uint32_t sQl = sb + AARR;
    const int nkt = qt + 1;

#define ALOAD(dst, src, trow)                                                 \
    do {                                                                      \
        _Pragma("unroll")                                                     \
        for (int i_ = 0; i_ < 4; i_++) {                                      \
            const int idx_ = tid + i_ * 128;                                  \
            const int r_ = idx_ >> 3, c_ = idx_ & 7;                          \
            cp16((dst) + r_ * AROWB + c_ * 16,                                \
                 (src) + (size_t)((trow) + r_) * D3 + c_ * 8);                \
        }                                                                     \
    } while (0)

#define AKV(kt_)                                                              \
    do {                                                                      \
        const uint32_t st_ = sb + 2 * AARR + ((kt_) & 1) * (4 * AARR);        \
        ALOAD(st_ + 0 * AARR, kh, (kt_) * 64);                                \
        ALOAD(st_ + 1 * AARR, kl, (kt_) * 64);                                \
        ALOAD(st_ + 2 * AARR, vh, (kt_) * 64);                                \
        ALOAD(st_ + 3 * AARR, vl, (kt_) * 64);                                \
    } while (0)

    ALOAD(sQh, qh, qt * 64);
    ALOAD(sQl, ql, qt * 64);
    AKV(0);
    cp_commit();
    if (nkt > 1) AKV(1);
    cp_commit();
    cp_wait1();
    __syncthreads();

    uint32_t qfh[4][4], qfl[4][4];
    {
        const uint32_t qa = (uint32_t)((w * 16 + (lane & 15)) * AROWB + ((lane >> 4) << 4));
        #pragma unroll
        for (int ks = 0; ks < 4; ks++) {
            LDSM4(qfh[ks][0], qfh[ks][1], qfh[ks][2], qfh[ks][3], sQh + qa + ks * 32);
            LDSM4(qfl[ks][0], qfl[ks][1], qfl[ks][2], qfl[ks][3], sQl + qa + ks * 32);
        }
    }

    float o[8][4];
    #pragma unroll
    for (int nb = 0; nb < 8; nb++)
        #pragma unroll
        for (int j = 0; j < 4; j++) o[nb][j] = 0.f;
    float m0 = -INFINITY, m1 = -INFINITY, l0 = 0.f, l1 = 0.f;

    const uint32_t kb_off = (uint32_t)((((lane >> 4) << 3) + (lane & 7)) * AROWB
                                       + (((lane >> 3) & 1) << 4));
    const uint32_t vb_off = (uint32_t)(((((lane >> 3) & 1) << 3) + (lane & 7)) * AROWB
                                       + ((lane >> 4) << 4));

    for (int kt = 0; kt < nkt; kt++) {
        const uint32_t stg = sb + 2 * AARR + (kt & 1) * (4 * AARR);

        float s[8][4];
        #pragma unroll
        for (int nb = 0; nb < 8; nb++)
            #pragma unroll
            for (int j = 0; j < 4; j++) s[nb][j] = 0.f;

        #pragma unroll
        for (int ks = 0; ks < 4; ks++) {
            uint32_t bhk[8][2], blk[8][2];
            #pragma unroll
            for (int nb2 = 0; nb2 < 4; nb2++) {
                const uint32_t ka = stg + kb_off + nb2 * (16 * AROWB) + ks * 32;
                LDSM4(bhk[2*nb2][0], bhk[2*nb2][1], bhk[2*nb2+1][0], bhk[2*nb2+1][1], ka);
                LDSM4(blk[2*nb2][0], blk[2*nb2][1], blk[2*nb2+1][0], blk[2*nb2+1][1], ka + AARR);
            }
            #pragma unroll
            for (int nb = 0; nb < 8; nb++) {
                MMA_BF16(s[nb], qfh[ks], bhk[nb]);
                MMA_BF16(s[nb], qfh[ks], blk[nb]);
                MMA_BF16(s[nb], qfl[ks], bhk[nb]);
            }
        }

        #pragma unroll
        for (int nb = 0; nb < 8; nb++)
            #pragma unroll
            for (int j = 0; j < 4; j++) s[nb][j] *= 0.125f;

        if (kt == qt) {
            const int r0 = w * 16 + (lane >> 2);
            #pragma unroll
            for (int nb = 0; nb < 8; nb++) {
                const int c0 = nb * 8 + (lane & 3) * 2;
                if (c0     > r0)     s[nb][0] = -1e30f;
                if (c0 + 1 > r0)     s[nb][1] = -1e30f;
                if (c0     > r0 + 8) s[nb][2] = -1e30f;
                if (c0 + 1 > r0 + 8) s[nb][3] = -1e30f;
            }
        }

        float mx0 = -INFINITY, mx1 = -INFINITY;
        #pragma unroll
        for (int nb = 0; nb < 8; nb++) {
            mx0 = fmaxf(mx0, fmaxf(s[nb][0], s[nb][1]));
            mx1 = fmaxf(mx1, fmaxf(s[nb][2], s[nb][3]));
        }
        mx0 = fmaxf(mx0, __shfl_xor_sync(0xffffffffu, mx0, 1));
        mx0 = fmaxf(mx0, __shfl_xor_sync(0xffffffffu, mx0, 2));
        mx1 = fmaxf(mx1, __shfl_xor_sync(0xffffffffu, mx1, 1));
        mx1 = fmaxf(mx1, __shfl_xor_sync(0xffffffffu, mx1, 2));

        const float mn0 = fmaxf(m0, mx0);
        const float mn1 = fmaxf(m1, mx1);
        const float al0 = __expf(m0 - mn0);
        const float al1 = __expf(m1 - mn1);
        m0 = mn0; m1 = mn1;

        float ls0 = 0.f, ls1 = 0.f;
        #pragma unroll
        for (int nb = 0; nb < 8; nb++) {
            s[nb][0] = __expf(s[nb][0] - mn0);
            s[nb][1] = __expf(s[nb][1] - mn0);
            s[nb][2] = __expf(s[nb][2] - mn1);
            s[nb][3] = __expf(s[nb][3] - mn1);
            ls0 += s[nb][0] + s[nb][1];
            ls1 += s[nb][2] + s[nb][3];
        }
        ls0 += __shfl_xor_sync(0xffffffffu, ls0, 1);
        ls0 += __shfl_xor_sync(0xffffffffu, ls0, 2);
        ls1 += __shfl_xor_sync(0xffffffffu, ls1, 1);
        ls1 += __shfl_xor_sync(0xffffffffu, ls1, 2);
        l0 = l0 * al0 + ls0;
        l1 = l1 * al1 + ls1;

        #pragma unroll
        for (int nb = 0; nb < 8; nb++) {
            o[nb][0] *= al0; o[nb][1] *= al0;
            o[nb][2] *= al1; o[nb][3] *= al1;
        }

        uint32_t pfh[4][4], pfl[4][4];
        #pragma unroll
        for (int t = 0; t < 4; t++) {
            __nv_bfloat16 h[8], lo_[8];
            #pragma unroll
            for (int j = 0; j < 4; j++) {
                split_bf16(s[2*t][j],   h[j],     lo_[j]);
                split_bf16(s[2*t+1][j], h[4 + j], lo_[4 + j]);
            }
            pfh[t][0] = pack_bf16(h[0], h[1]);
            pfh[t][1] = pack_bf16(h[2], h[3]);
            pfh[t][2] = pack_bf16(h[4], h[5]);
            pfh[t][3] = pack_bf16(h[6], h[7]);
            pfl[t][0] = pack_bf16(lo_[0], lo_[1]);
            pfl[t][1] = pack_bf16(lo_[2], lo_[3]);
            pfl[t][2] = pack_bf16(lo_[4], lo_[5]);
            pfl[t][3] = pack_bf16(lo_[6], lo_[7]);
        }

        const uint32_t vbase = stg + 2 * AARR;
        #pragma unroll
        for (int t = 0; t < 4; t++) {
            uint32_t bvh[8][2], bvl[8][2];
            #pragma unroll
            for (int j2 = 0; j2 < 4; j2++) {
                const uint32_t va = vbase + vb_off + t * (16 * AROWB) + j2 * 32;
                LDSM4T(bvh[2*j2][0], bvh[2*j2][1], bvh[2*j2+1][0], bvh[2*j2+1][1], va);
                LDSM4T(bvl[2*j2][0], bvl[2*j2][1], bvl[2*j2+1][0], bvl[2*j2+1][1], va + AARR);
            }
            #pragma unroll
            for (int nb = 0; nb < 8; nb++) {
                MMA_BF16(o[nb], pfh[t], bvh[nb]);
                MMA_BF16(o[nb], pfh[t], bvl[nb]);
                MMA_BF16(o[nb], pfl[t], bvh[nb]);
            }
        }

        __syncthreads();
        if (kt + 2 < nkt) AKV(kt + 2);
        cp_commit();
        cp_wait1();
        __syncthreads();
    }

#undef AKV
#undef ALOAD

    const float inv0 = 1.0f / l0;
    const float inv1 = 1.0f / l1;
    const int rr0 = qt * 64 + w * 16 + (lane >> 2);
    #pragma unroll
    for (int nb = 0; nb < 8; nb++) {
        const int col = hh * HDIM + nb * 8 + (lane & 3) * 2;
        const size_t t0 = (size_t)(bb * TT + rr0) * DD + col;
        const size_t t1 = (size_t)(bb * TT + rr0 + 8) * DD + col;
        __nv_bfloat16 h0, lo0, h1, lo1;
        split_bf16(o[nb][0] * inv0, h0, lo0);
        split_bf16(o[nb][1] * inv0, h1, lo1);
        *(uint32_t*)(yhi + t0) = pack_bf16(h0, h1);
        *(uint32_t*)(ylo + t0) = pack_bf16(lo0, lo1);
        split_bf16(o[nb][2] * inv1, h0, lo0);
        split_bf16(o[nb][3] * inv1, h1, lo1);
        *(uint32_t*)(yhi + t1) = pack_bf16(h0, h1);
        *(uint32_t*)(ylo + t1) = pack_bf16(lo0, lo1);
    }
}

// ---------------------------------------------------------------------------
extern "C" void kernel_launch(void* const* d_in, const int* in_sizes, int n_in,
                              void* d_out, int out_size) {
    const float* x      = (const float*)d_in[0];
    const float* w_attn = (const float*)d_in[1];
    const float* w_proj = (const float*)d_in[2];
    const float* w_fc   = (const float*)d_in[3];
    const float* w_out  = (const float*)d_in[4];
    const float* ln1_g  = (const float*)d_in[5];
    const float* ln1_b  = (const float*)d_in[6];
    const float* ln2_g  = (const float*)d_in[7];
    const float* ln2_b  = (const float*)d_in[8];
    float* out = (float*)d_out;

    float* p_x2;
    __nv_bfloat16 *p_xn_hi, *p_xn_lo, *p_qkv_hi, *p_qkv_lo;
    __nv_bfloat16 *p_y_hi, *p_y_lo, *p_fc_hi, *p_fc_lo;
    __nv_bfloat16 *p_wa_hi, *p_wa_lo, *p_wp_hi, *p_wp_lo;
    __nv_bfloat16 *p_wf_hi, *p_wf_lo, *p_wo_hi, *p_wo_lo;
    cudaGetSymbolAddress((void**)&p_x2,     g_x2);
    cudaGetSymbolAddress((void**)&p_xn_hi,  g_xn_hi);
    cudaGetSymbolAddress((void**)&p_xn_lo,  g_xn_lo);
    cudaGetSymbolAddress((void**)&p_qkv_hi, g_qkv_hi);
    cudaGetSymbolAddress((void**)&p_qkv_lo, g_qkv_lo);
    cudaGetSymbolAddress((void**)&p_y_hi,   g_y_hi);
    cudaGetSymbolAddress((void**)&p_y_lo,   g_y_lo);
    cudaGetSymbolAddress((void**)&p_fc_hi,  g_fc_hi);
    cudaGetSymbolAddress((void**)&p_fc_lo,  g_fc_lo);
    cudaGetSymbolAddress((void**)&p_wa_hi,  g_wattn_hi);
    cudaGetSymbolAddress((void**)&p_wa_lo,  g_wattn_lo);
    cudaGetSymbolAddress((void**)&p_wp_hi,  g_wproj_hi);
    cudaGetSymbolAddress((void**)&p_wp_lo,  g_wproj_lo);
    cudaGetSymbolAddress((void**)&p_wf_hi,  g_wfc_hi);
    cudaGetSymbolAddress((void**)&p_wf_lo,  g_wfc_lo);
    cudaGetSymbolAddress((void**)&p_wo_hi,  g_wout_hi);
    cudaGetSymbolAddress((void**)&p_wo_lo,  g_wout_lo);

    cudaFuncSetAttribute(attn_kernel,
                         cudaFuncAttributeMaxDynamicSharedMemorySize, ATT_SMEM);
    cudaFuncSetAttribute(mm_kernel<1>,
                         cudaFuncAttributeMaxDynamicSharedMemorySize, MM_SMEM);
    cudaFuncSetAttribute(mm_kernel<2>,
                         cudaFuncAttributeMaxDynamicSharedMemorySize, MM_SMEM);
    cudaFuncSetAttribute(mm_kernel<3>,
                         cudaFuncAttributeMaxDynamicSharedMemorySize, MM_SMEM);

    const dim3 tb(32, 8);

    wtrans_kernel<<<dim3(D3 / 32, DD / 32), tb>>>(w_attn, p_wa_hi, p_wa_lo, DD, D3);
    wtrans_kernel<<<dim3(DD / 32, DD / 32), tb>>>(w_proj, p_wp_hi, p_wp_lo, DD, DD);
    wtrans_kernel<<<dim3(D4 / 32, DD / 32), tb>>>(w_fc,   p_wf_hi, p_wf_lo, DD, D4);
    wtrans_kernel<<<dim3(DD / 32, D4 / 32), tb>>>(w_out,  p_wo_hi, p_wo_lo, D4, DD);

    ln_kernel<<<ROWS, 256>>>(x, ln1_g, ln1_b, p_xn_hi, p_xn_lo);

    mm_kernel<3><<<dim3(D3 / 128, ROWS / 128), 256, MM_SMEM>>>(
        p_xn_hi, p_xn_lo, p_wa_hi, p_wa_lo, nullptr, nullptr, p_qkv_hi, p_qkv_lo,
        ROWS, D3, DD);

    attn_kernel<<<dim3(TT / 64, BB * HH), 128, ATT_SMEM>>>(
        p_qkv_hi, p_qkv_lo, p_y_hi, p_y_lo);

    mm_kernel<1><<<dim3(DD / 128, ROWS / 128), 256, MM_SMEM>>>(
        p_y_hi, p_y_lo, p_wp_hi, p_wp_lo, x, p_x2, nullptr, nullptr,
        ROWS, DD, DD);

    ln_kernel<<<ROWS, 256>>>(p_x2, ln2_g, ln2_b, p_xn_hi, p_xn_lo);

    mm_kernel<2><<<dim3(D4 / 128, ROWS / 128), 256, MM_SMEM>>>(
        p_xn_hi, p_xn_lo, p_wf_hi, p_wf_lo, nullptr, nullptr, p_fc_hi, p_fc_lo,
        ROWS, D4, DD);

    mm_kernel<1><<<dim3(DD / 128, ROWS / 128), 256, MM_SMEM>>>(
        p_fc_hi, p_fc_lo, p_wo_hi, p_wo_lo, p_x2, out, nullptr, nullptr,
        ROWS, DD, D4);
}